// round 3
// baseline (speedup 1.0000x reference)
#include <cuda_runtime.h>
#include <math.h>
#include <stdint.h>

#define N_ROWS 32768
#define DIM    256
#define KCODES 1024

// ---------------- device scratch ----------------
__device__ float g_S[(size_t)N_ROWS * KCODES];     // s[n,k] = |c_k|^2 - 2 x_n.c_k  (134 MB)
__device__ float g_A[(size_t)N_ROWS * 512];        // [Xhi | Xlo]        (64 MB)
__device__ float g_B[(size_t)KCODES * 768];        // [Chi | Clo | Chi]  (3 MB)
__device__ float g_c2[KCODES];
__device__ float g_probs[KCODES];
__device__ float g_scal[2];

// ---------------- PTX helpers (sm_100-safe: no 'a' features) ----------------
__device__ __forceinline__ uint32_t smem_u32(const void* p) {
    uint32_t a;
    asm("{ .reg .u64 t; cvta.to.shared.u64 t, %1; cvt.u32.u64 %0, t; }" : "=r"(a) : "l"(p));
    return a;
}
__device__ __forceinline__ void cp_async16(uint32_t dst, const void* src) {
    asm volatile("cp.async.cg.shared.global [%0], [%1], 16;" :: "r"(dst), "l"(src) : "memory");
}
__device__ __forceinline__ void cp_commit() {
    asm volatile("cp.async.commit_group;" ::: "memory");
}
template <int N>
__device__ __forceinline__ void cp_wait() {
    asm volatile("cp.async.wait_group %0;" :: "n"(N) : "memory");
}
__device__ __forceinline__ float tf32_rna(float x) {
    uint32_t b;
    asm("cvt.rna.tf32.f32 %0, %1;" : "=r"(b) : "f"(x));
    return __uint_as_float(b);
}
__device__ __forceinline__ void mma_tf32(float* d, const uint32_t* a, const uint32_t* b) {
    asm volatile(
        "mma.sync.aligned.m16n8k8.row.col.f32.tf32.tf32.f32 "
        "{%0,%1,%2,%3}, {%4,%5,%6,%7}, {%8,%9}, {%0,%1,%2,%3};"
        : "+f"(d[0]), "+f"(d[1]), "+f"(d[2]), "+f"(d[3])
        : "r"(a[0]), "r"(a[1]), "r"(a[2]), "r"(a[3]), "r"(b[0]), "r"(b[1]));
}

// ---------------- init: zero accumulators + codebook norms ----------------
__global__ void vq_init_kernel(const float* __restrict__ CB) {
    int gtid = blockIdx.x * blockDim.x + threadIdx.x;
    if (gtid < KCODES) g_probs[gtid] = 0.f;
    if (gtid < 2) g_scal[gtid] = 0.f;
    int wid = gtid >> 5;
    int lane = gtid & 31;
    if (wid < KCODES) {
        const float* c = CB + (size_t)wid * DIM;
        float s = 0.f;
        for (int i = lane; i < DIM; i += 32) { float v = c[i]; s += v * v; }
        #pragma unroll
        for (int o = 16; o; o >>= 1) s += __shfl_down_sync(0xffffffffu, s, o);
        if (lane == 0) g_c2[wid] = s;
    }
}

// ---------------- prep: tf32 hi/lo split ----------------
__global__ __launch_bounds__(256)
void vq_prep_a(const float* __restrict__ X) {
    int idx = blockIdx.x * blockDim.x + threadIdx.x;
    int n = idx >> 8;
    int d = idx & 255;
    float x = X[idx];
    float hi = tf32_rna(x);
    float lo = tf32_rna(x - hi);
    float* row = g_A + (size_t)n * 512;
    row[d]       = hi;
    row[256 + d] = lo;
}
__global__ __launch_bounds__(256)
void vq_prep_b(const float* __restrict__ CB) {
    int idx = blockIdx.x * blockDim.x + threadIdx.x;
    int k = idx >> 8;
    int d = idx & 255;
    float x = CB[idx];
    float hi = tf32_rna(x);
    float lo = tf32_rna(x - hi);
    float* row = g_B + (size_t)k * 768;
    row[d]       = hi;
    row[256 + d] = lo;
    row[512 + d] = hi;
}

// ---------------- TF32 mma.sync GEMM: s = c2[k] - 2*dot ----------------
// BM=128, BN=256, BK=16, 512 threads (16 warps, 4x4), warp tile 32x64, 3 stages.
// Chunk c pairing: c in [0,16): A-hi x B-Chi ; [16,32): A-hi x B-Clo ; [32,48): A-lo x B-Chi
#define BMg     128
#define BNg     256
#define BKg     16
#define CHUNKS  48
#define STAGES  3
#define AS_STRIDE 20                 // floats per row (16 + 4 pad) -> conflict-free frags
#define A_STAGE_FLOATS (BMg * AS_STRIDE)      // 2560
#define B_STAGE_FLOATS (BNg * AS_STRIDE)      // 5120
#define STAGE_FLOATS   (A_STAGE_FLOATS + B_STAGE_FLOATS)   // 7680 (30720 B)
#define GEMM_SMEM_FLOATS (STAGES * STAGE_FLOATS + BNg)     // + c2 tile

__global__ __launch_bounds__(512, 1)
void vq_mma_gemm() {
    extern __shared__ __align__(16) float smem[];
    float* s_c2 = smem + STAGES * STAGE_FLOATS;

    const int tid  = threadIdx.x;
    const int lane = tid & 31;
    const int wid  = tid >> 5;
    const int warp_row = wid & 3;     // M direction (4)
    const int warp_col = wid >> 2;    // N direction (4)
    const int bn = blockIdx.x;        // 0..3
    const int bm = blockIdx.y;        // 0..255

    if (tid < BNg) s_c2[tid] = g_c2[bn * BNg + tid];

    const float* Abase = g_A + (size_t)(bm * BMg) * 512;
    const float* Bbase = g_B + (size_t)(bn * BNg) * 768;
    const uint32_t sbase = smem_u32(smem);

    // async chunk loader
    auto load_chunk = [&](int c) {
        const int stage = c % STAGES;
        const uint32_t dA = sbase + stage * (STAGE_FLOATS * 4);
        const uint32_t dB = dA + A_STAGE_FLOATS * 4;
        const int a_col = ((c >= 32) ? 256 : 0) + (c & 15) * 16;
        const int b_col = c * 16;
        {   // A: 128 rows x 16 floats = 512 x 16B; one per thread
            int row = tid >> 2, c16 = tid & 3;
            cp_async16(dA + row * (AS_STRIDE * 4) + c16 * 16,
                       Abase + (size_t)row * 512 + a_col + c16 * 4);
        }
        #pragma unroll
        for (int i = 0; i < 2; i++) {   // B: 256 rows x 16 floats = 1024 x 16B; two per thread
            int idx = tid + i * 512;
            int row = idx >> 2, c16 = idx & 3;
            cp_async16(dB + row * (AS_STRIDE * 4) + c16 * 16,
                       Bbase + (size_t)row * 768 + b_col + c16 * 4);
        }
        cp_commit();
    };

    float acc[2][8][4];
    #pragma unroll
    for (int mt = 0; mt < 2; mt++)
        #pragma unroll
        for (int nn = 0; nn < 8; nn++)
            #pragma unroll
            for (int j = 0; j < 4; j++) acc[mt][nn][j] = 0.f;

    load_chunk(0);
    load_chunk(1);

    const int r4 = lane >> 2;   // 0..7
    const int c4 = lane & 3;    // 0..3

    for (int c = 0; c < CHUNKS; c++) {
        cp_wait<1>();
        __syncthreads();
        if (c + 2 < CHUNKS) load_chunk(c + 2);

        const int stage = c % STAGES;
        const uint32_t* As = (const uint32_t*)(smem + stage * STAGE_FLOATS);
        const uint32_t* Bs = (const uint32_t*)(smem + stage * STAGE_FLOATS + A_STAGE_FLOATS);

        #pragma unroll
        for (int ks = 0; ks < 2; ks++) {
            const int kb = ks * 8;
            uint32_t afr[2][4];
            #pragma unroll
            for (int mt = 0; mt < 2; mt++) {
                int row0 = warp_row * 32 + mt * 16 + r4;
                afr[mt][0] = As[row0 * AS_STRIDE + kb + c4];
                afr[mt][1] = As[(row0 + 8) * AS_STRIDE + kb + c4];
                afr[mt][2] = As[row0 * AS_STRIDE + kb + c4 + 4];
                afr[mt][3] = As[(row0 + 8) * AS_STRIDE + kb + c4 + 4];
            }
            #pragma unroll
            for (int nn = 0; nn < 8; nn++) {
                uint32_t bfr[2];
                int ncol = warp_col * 64 + nn * 8 + r4;
                bfr[0] = Bs[ncol * AS_STRIDE + kb + c4];
                bfr[1] = Bs[ncol * AS_STRIDE + kb + c4 + 4];
                mma_tf32(acc[0][nn], afr[0], bfr);
                mma_tf32(acc[1][nn], afr[1], bfr);
            }
        }
        __syncthreads();
    }

    // epilogue: s = c2[k] - 2*acc  (C frag: rows r4, r4+8; cols 2*c4, 2*c4+1)
    #pragma unroll
    for (int mt = 0; mt < 2; mt++) {
        int row0 = bm * BMg + warp_row * 32 + mt * 16 + r4;
        #pragma unroll
        for (int nn = 0; nn < 8; nn++) {
            int ncl = warp_col * 64 + nn * 8 + c4 * 2;        // local col in [0,256)
            int col = bn * BNg + ncl;
            float2 v0, v1;
            v0.x = s_c2[ncl]     - 2.f * acc[mt][nn][0];
            v0.y = s_c2[ncl + 1] - 2.f * acc[mt][nn][1];
            v1.x = s_c2[ncl]     - 2.f * acc[mt][nn][2];
            v1.y = s_c2[ncl + 1] - 2.f * acc[mt][nn][3];
            *(float2*)(g_S + (size_t)row0 * KCODES + col)       = v0;
            *(float2*)(g_S + (size_t)(row0 + 8) * KCODES + col) = v1;
        }
    }
}

// ---------------- per-row: argmin, softmax stats, gather, loss partials ----------------
#define ROWS_PER_BLOCK 32
__global__ __launch_bounds__(256)
void vq_row_kernel(const float* __restrict__ X, const float* __restrict__ CB,
                   float* __restrict__ out_q, float* __restrict__ out_idx) {
    __shared__ float s_ra[8], s_rb[8], s_rc[8];
    __shared__ int   s_ri[8];
    __shared__ float s_min, s_Z;
    __shared__ int   s_idx;

    const int t = threadIdx.x;
    const int lane = t & 31;
    const int wid = t >> 5;

    float pacc0 = 0.f, pacc1 = 0.f, pacc2 = 0.f, pacc3 = 0.f;
    float ent_sum = 0.f, lat_sum = 0.f;

    for (int r = 0; r < ROWS_PER_BLOCK; r++) {
        const int n = blockIdx.x * ROWS_PER_BLOCK + r;
        const float* srow = g_S + (size_t)n * KCODES;
        float s0 = srow[t];
        float s1v = srow[t + 256];
        float s2 = srow[t + 512];
        float s3 = srow[t + 768];

        float mv = s0; int mi = t;
        if (s1v < mv) { mv = s1v; mi = t + 256; }
        if (s2  < mv) { mv = s2;  mi = t + 512; }
        if (s3  < mv) { mv = s3;  mi = t + 768; }

        #pragma unroll
        for (int o = 16; o; o >>= 1) {
            float ov = __shfl_down_sync(0xffffffffu, mv, o);
            int   oi = __shfl_down_sync(0xffffffffu, mi, o);
            if (ov < mv || (ov == mv && oi < mi)) { mv = ov; mi = oi; }
        }
        if (lane == 0) { s_ra[wid] = mv; s_ri[wid] = mi; }
        __syncthreads();
        if (wid == 0) {
            float v = (lane < 8) ? s_ra[lane] : 3.4e38f;
            int  ii = (lane < 8) ? s_ri[lane] : 0x7fffffff;
            #pragma unroll
            for (int o = 4; o; o >>= 1) {
                float ov = __shfl_down_sync(0xffffffffu, v, o);
                int   oi = __shfl_down_sync(0xffffffffu, ii, o);
                if (ov < v || (ov == v && oi < ii)) { v = ov; ii = oi; }
            }
            if (lane == 0) { s_min = v; s_idx = ii; }
        }
        __syncthreads();
        const float smin = s_min;
        const int idx = s_idx;

        float d0 = s0 - smin, d1 = s1v - smin, d2 = s2 - smin, d3 = s3 - smin;
        float e0 = expf(-100.f * d0);
        float e1 = expf(-100.f * d1);
        float e2 = expf(-100.f * d2);
        float e3 = expf(-100.f * d3);
        float z  = e0 + e1 + e2 + e3;
        float s1sum = e0 * d0 + e1 * d1 + e2 * d2 + e3 * d3;

        float cv = CB[(size_t)idx * DIM + t];
        float xv = X[(size_t)n * DIM + t];
        out_q[(size_t)n * DIM + t] = cv;
        float df = cv - xv;
        float d2sum = df * df;

        #pragma unroll
        for (int o = 16; o; o >>= 1) {
            z     += __shfl_down_sync(0xffffffffu, z, o);
            s1sum += __shfl_down_sync(0xffffffffu, s1sum, o);
            d2sum += __shfl_down_sync(0xffffffffu, d2sum, o);
        }
        if (lane == 0) { s_ra[wid] = z; s_rb[wid] = s1sum; s_rc[wid] = d2sum; }
        __syncthreads();
        if (wid == 0) {
            float a = (lane < 8) ? s_ra[lane] : 0.f;
            float b = (lane < 8) ? s_rb[lane] : 0.f;
            float cc = (lane < 8) ? s_rc[lane] : 0.f;
            #pragma unroll
            for (int o = 4; o; o >>= 1) {
                a += __shfl_down_sync(0xffffffffu, a, o);
                b += __shfl_down_sync(0xffffffffu, b, o);
                cc += __shfl_down_sync(0xffffffffu, cc, o);
            }
            if (lane == 0) {
                s_Z = a;
                ent_sum += 100.f * (b / a) + logf(a);
                lat_sum += cc;
            }
        }
        __syncthreads();
        const float Z = s_Z;
        pacc0 += e0 / Z;
        pacc1 += e1 / Z;
        pacc2 += e2 / Z;
        pacc3 += e3 / Z;

        if (t == 0 && out_idx) out_idx[n] = (float)idx;
        __syncthreads();
    }

    atomicAdd(&g_probs[t],       pacc0);
    atomicAdd(&g_probs[t + 256], pacc1);
    atomicAdd(&g_probs[t + 512], pacc2);
    atomicAdd(&g_probs[t + 768], pacc3);
    if (t == 0) {
        atomicAdd(&g_scal[0], lat_sum);
        atomicAdd(&g_scal[1], ent_sum);
    }
}

// ---------------- finalize ----------------
__global__ void vq_finalize_kernel(float* __restrict__ out_loss) {
    __shared__ float warp_s[32];
    const int t = threadIdx.x;
    const int lane = t & 31;
    const int wid = t >> 5;

    float p = g_probs[t] * (1.0f / (float)N_ROWS);
    float contrib = -p * logf(p + 1e-5f);
    #pragma unroll
    for (int o = 16; o; o >>= 1) contrib += __shfl_down_sync(0xffffffffu, contrib, o);
    if (lane == 0) warp_s[wid] = contrib;
    __syncthreads();
    if (wid == 0) {
        float v = warp_s[lane];
        #pragma unroll
        for (int o = 16; o; o >>= 1) v += __shfl_down_sync(0xffffffffu, v, o);
        if (lane == 0 && out_loss) {
            float avg_entropy = v;
            float sample_entropy = g_scal[1] * (1.0f / (float)N_ROWS);
            float mean_lat = g_scal[0] * (1.0f / ((float)N_ROWS * (float)DIM));
            float ent_loss = sample_entropy - avg_entropy;
            *out_loss = 1.25f * mean_lat + 0.1f * ent_loss;
        }
    }
}

// ---------------- launch ----------------
extern "C" void kernel_launch(void* const* d_in, const int* in_sizes, int n_in,
                              void* d_out, int out_size) {
    const float* X  = (const float*)d_in[0];
    const float* CB = (const float*)d_in[1];
    float* out = (float*)d_out;

    float* out_q    = out;
    float* out_loss = (out_size >= N_ROWS * DIM + 1) ? (out + (size_t)N_ROWS * DIM) : nullptr;
    float* out_idx  = (out_size >= N_ROWS * DIM + 1 + N_ROWS) ? (out + (size_t)N_ROWS * DIM + 1) : nullptr;

    const int gemm_smem = GEMM_SMEM_FLOATS * 4;   // ~94 KB
    static int smem_set = 0;
    if (!smem_set) {
        cudaFuncSetAttribute(vq_mma_gemm, cudaFuncAttributeMaxDynamicSharedMemorySize, gemm_smem);
        smem_set = 1;
    }

    vq_init_kernel<<<128, 256>>>(CB);
    vq_prep_a<<<(N_ROWS * DIM) / 256, 256>>>(X);
    vq_prep_b<<<(KCODES * DIM) / 256, 256>>>(CB);
    dim3 g(KCODES / BNg, N_ROWS / BMg);
    vq_mma_gemm<<<g, 512, gemm_smem>>>();
    vq_row_kernel<<<N_ROWS / ROWS_PER_BLOCK, 256>>>(X, CB, out_q, out_idx);
    vq_finalize_kernel<<<1, 1024>>>(out_loss);
}

// round 4
// speedup vs baseline: 1.7095x; 1.7095x over previous
#include <cuda_runtime.h>
#include <cuda_fp16.h>
#include <math.h>
#include <stdint.h>

#define N_ROWS 32768
#define DIM    256
#define KCODES 1024

// ---------------- device scratch ----------------
__device__ float  g_S[(size_t)N_ROWS * KCODES];    // s[n,k] = |c_k|^2 - 2 x.c   (134 MB)
__device__ __half g_Ah[(size_t)N_ROWS * 512];      // [Xhi | Xlo]        (32 MB)
__device__ __half g_Bh[(size_t)KCODES * 768];      // [Chi | Clo | Chi]  (1.5 MB)
__device__ float  g_c2[KCODES];
__device__ float  g_probs[KCODES];
__device__ float  g_scal[2];

// ---------------- PTX helpers (sm_100-safe, no 'a' features) ----------------
__device__ __forceinline__ uint32_t smem_u32(const void* p) {
    uint32_t a;
    asm("{ .reg .u64 t; cvta.to.shared.u64 t, %1; cvt.u32.u64 %0, t; }" : "=r"(a) : "l"(p));
    return a;
}
__device__ __forceinline__ void cp_async16(uint32_t dst, const void* src) {
    asm volatile("cp.async.cg.shared.global [%0], [%1], 16;" :: "r"(dst), "l"(src) : "memory");
}
__device__ __forceinline__ void cp_commit() {
    asm volatile("cp.async.commit_group;" ::: "memory");
}
template <int N>
__device__ __forceinline__ void cp_wait() {
    asm volatile("cp.async.wait_group %0;" :: "n"(N) : "memory");
}
__device__ __forceinline__ void ldsm4(uint32_t* r, uint32_t addr) {
    asm volatile("ldmatrix.sync.aligned.m8n8.x4.shared.b16 {%0,%1,%2,%3}, [%4];"
                 : "=r"(r[0]), "=r"(r[1]), "=r"(r[2]), "=r"(r[3]) : "r"(addr));
}
__device__ __forceinline__ void mma_f16(float* d, const uint32_t* a, uint32_t b0, uint32_t b1) {
    asm volatile(
        "mma.sync.aligned.m16n8k16.row.col.f32.f16.f16.f32 "
        "{%0,%1,%2,%3}, {%4,%5,%6,%7}, {%8,%9}, {%0,%1,%2,%3};"
        : "+f"(d[0]), "+f"(d[1]), "+f"(d[2]), "+f"(d[3])
        : "r"(a[0]), "r"(a[1]), "r"(a[2]), "r"(a[3]), "r"(b0), "r"(b1));
}

// ---------------- init: zero accumulators + codebook norms ----------------
__global__ void vq_init_kernel(const float* __restrict__ CB) {
    int gtid = blockIdx.x * blockDim.x + threadIdx.x;
    if (gtid < KCODES) g_probs[gtid] = 0.f;
    if (gtid < 2) g_scal[gtid] = 0.f;
    int wid = gtid >> 5;
    int lane = gtid & 31;
    if (wid < KCODES) {
        const float* c = CB + (size_t)wid * DIM;
        float s = 0.f;
        for (int i = lane; i < DIM; i += 32) { float v = c[i]; s += v * v; }
        #pragma unroll
        for (int o = 16; o; o >>= 1) s += __shfl_down_sync(0xffffffffu, s, o);
        if (lane == 0) g_c2[wid] = s;
    }
}

// ---------------- prep: fp16 hi/lo split ----------------
__global__ __launch_bounds__(256)
void vq_prep_a(const float* __restrict__ X) {
    int idx = blockIdx.x * blockDim.x + threadIdx.x;   // handles 2 elems
    int i2 = idx * 2;
    int n = i2 >> 8;
    int d = i2 & 255;
    float2 x = *(const float2*)(X + i2);
    __half h0 = __float2half_rn(x.x);
    __half h1 = __float2half_rn(x.y);
    __half l0 = __float2half_rn(x.x - __half2float(h0));
    __half l1 = __float2half_rn(x.y - __half2float(h1));
    __half* row = g_Ah + (size_t)n * 512;
    *(half2*)(row + d)       = __halves2half2(h0, h1);
    *(half2*)(row + 256 + d) = __halves2half2(l0, l1);
}
__global__ __launch_bounds__(256)
void vq_prep_b(const float* __restrict__ CB) {
    int idx = blockIdx.x * blockDim.x + threadIdx.x;
    int i2 = idx * 2;
    int k = i2 >> 8;
    int d = i2 & 255;
    float2 x = *(const float2*)(CB + i2);
    __half h0 = __float2half_rn(x.x);
    __half h1 = __float2half_rn(x.y);
    __half l0 = __float2half_rn(x.x - __half2float(h0));
    __half l1 = __float2half_rn(x.y - __half2float(h1));
    __half* row = g_Bh + (size_t)k * 768;
    *(half2*)(row + d)       = __halves2half2(h0, h1);
    *(half2*)(row + 256 + d) = __halves2half2(l0, l1);
    *(half2*)(row + 512 + d) = __halves2half2(h0, h1);
}

// ---------------- fp16 mma.sync GEMM: s = c2[k] - 2*dot ----------------
// BM=128, BN=256, BK=32 halves, 512 threads (16 warps 4x4), warp tile 32x64.
// 24 chunks over K'=768: c<8: Ahi x Chi ; 8<=c<16: Ahi x Clo ; c>=16: Alo x Chi.
#define BMg 128
#define BNg 256
#define CHUNKS 24
#define STAGES 3
#define SH 40                                   // halves per smem row (80 B)
#define A_STAGE_H (BMg * SH)                    // 5120 halves
#define B_STAGE_H (BNg * SH)                    // 10240 halves
#define STAGE_H   (A_STAGE_H + B_STAGE_H)       // 15360 halves (30720 B)
#define GEMM_SMEM_BYTES (STAGES * STAGE_H * 2 + BNg * 4)

__global__ __launch_bounds__(512, 1)
void vq_mma_gemm() {
    extern __shared__ __align__(16) __half smem[];
    float* s_c2 = (float*)(smem + STAGES * STAGE_H);

    const int tid  = threadIdx.x;
    const int lane = tid & 31;
    const int wid  = tid >> 5;
    const int warp_row = wid & 3;
    const int warp_col = wid >> 2;
    const int bn = blockIdx.x;      // 0..3
    const int bm = blockIdx.y;      // 0..255

    if (tid < BNg) s_c2[tid] = g_c2[bn * BNg + tid];

    const __half* Abase = g_Ah + (size_t)(bm * BMg) * 512;
    const __half* Bbase = g_Bh + (size_t)(bn * BNg) * 768;
    const uint32_t sbase = smem_u32(smem);

    auto load_chunk = [&](int c) {
        const int stage = c % STAGES;
        const uint32_t dA = sbase + stage * (STAGE_H * 2);
        const uint32_t dB = dA + A_STAGE_H * 2;
        const int phase = c >> 3;
        const int acol = (phase == 2 ? 256 : 0) + (c & 7) * 32;
        const int bcol = c * 32;
        {   // A: 128 rows x 64 B = 512 x 16B
            int row = tid >> 2, c16 = tid & 3;
            cp_async16(dA + row * (SH * 2) + c16 * 16,
                       Abase + (size_t)row * 512 + acol + c16 * 8);
        }
        #pragma unroll
        for (int i = 0; i < 2; i++) {   // B: 256 rows x 64 B = 1024 x 16B
            int idx = tid + i * 512;
            int row = idx >> 2, c16 = idx & 3;
            cp_async16(dB + row * (SH * 2) + c16 * 16,
                       Bbase + (size_t)row * 768 + bcol + c16 * 8);
        }
        cp_commit();
    };

    float acc[2][8][4];
    #pragma unroll
    for (int mt = 0; mt < 2; mt++)
        #pragma unroll
        for (int nn = 0; nn < 8; nn++)
            #pragma unroll
            for (int j = 0; j < 4; j++) acc[mt][nn][j] = 0.f;

    load_chunk(0);
    load_chunk(1);

    const int grp = lane >> 3;      // ldmatrix address group 0..3
    const int rin = lane & 7;

    for (int c = 0; c < CHUNKS; c++) {
        cp_wait<1>();
        __syncthreads();
        if (c + 2 < CHUNKS) load_chunk(c + 2);

        const int stage = c % STAGES;
        const uint32_t aS = sbase + stage * (STAGE_H * 2);
        const uint32_t bS = aS + A_STAGE_H * 2;

        #pragma unroll
        for (int ks = 0; ks < 2; ks++) {
            const uint32_t kbyte = ks * 32;   // 16 halves per mma step
            // A fragments: groups (m+0/k0),(m+8/k0),(m+0/k8),(m+8/k8)
            uint32_t a[2][4];
            #pragma unroll
            for (int mt = 0; mt < 2; mt++) {
                int arow = warp_row * 32 + mt * 16 + ((grp & 1) << 3) + rin;
                ldsm4(a[mt], aS + arow * (SH * 2) + kbyte + (grp >> 1) * 16);
            }
            // B fragments: groups (n+0/k0),(n+0/k8),(n+8/k0),(n+8/k8)
            uint32_t b[8][2];
            #pragma unroll
            for (int np = 0; np < 4; np++) {
                int brow = warp_col * 64 + np * 16 + ((grp >> 1) << 3) + rin;
                uint32_t b4[4];
                ldsm4(b4, bS + brow * (SH * 2) + kbyte + (grp & 1) * 16);
                b[np * 2][0]     = b4[0]; b[np * 2][1]     = b4[1];
                b[np * 2 + 1][0] = b4[2]; b[np * 2 + 1][1] = b4[3];
            }
            #pragma unroll
            for (int nn = 0; nn < 8; nn++) {
                mma_f16(acc[0][nn], a[0], b[nn][0], b[nn][1]);
                mma_f16(acc[1][nn], a[1], b[nn][0], b[nn][1]);
            }
        }
        __syncthreads();
    }

    // epilogue: s = c2[k] - 2*acc  (C frag rows r4,r4+8; cols 2c4,2c4+1)
    const int r4 = lane >> 2;
    const int c4 = lane & 3;
    #pragma unroll
    for (int mt = 0; mt < 2; mt++) {
        int row0 = bm * BMg + warp_row * 32 + mt * 16 + r4;
        #pragma unroll
        for (int nn = 0; nn < 8; nn++) {
            int ncl = warp_col * 64 + nn * 8 + c4 * 2;
            int col = bn * BNg + ncl;
            float2 v0, v1;
            v0.x = s_c2[ncl]     - 2.f * acc[mt][nn][0];
            v0.y = s_c2[ncl + 1] - 2.f * acc[mt][nn][1];
            v1.x = s_c2[ncl]     - 2.f * acc[mt][nn][2];
            v1.y = s_c2[ncl + 1] - 2.f * acc[mt][nn][3];
            *(float2*)(g_S + (size_t)row0 * KCODES + col)       = v0;
            *(float2*)(g_S + (size_t)(row0 + 8) * KCODES + col) = v1;
        }
    }
}

// ---------------- per-row: argmin, softmax stats, gather, loss partials ----------------
#define ROWS_PER_BLOCK 32
__global__ __launch_bounds__(256)
void vq_row_kernel(const float* __restrict__ X, const float* __restrict__ CB,
                   float* __restrict__ out_q, float* __restrict__ out_idx) {
    __shared__ float s_ra[8], s_rb[8], s_rc[8];
    __shared__ int   s_ri[8];
    __shared__ float s_min, s_Z;
    __shared__ int   s_idx;

    const int t = threadIdx.x;
    const int lane = t & 31;
    const int wid = t >> 5;

    float pacc0 = 0.f, pacc1 = 0.f, pacc2 = 0.f, pacc3 = 0.f;
    float ent_sum = 0.f, lat_sum = 0.f;

    for (int r = 0; r < ROWS_PER_BLOCK; r++) {
        const int n = blockIdx.x * ROWS_PER_BLOCK + r;
        const float* srow = g_S + (size_t)n * KCODES;
        float s0 = srow[t];
        float s1v = srow[t + 256];
        float s2 = srow[t + 512];
        float s3 = srow[t + 768];

        float mv = s0; int mi = t;
        if (s1v < mv) { mv = s1v; mi = t + 256; }
        if (s2  < mv) { mv = s2;  mi = t + 512; }
        if (s3  < mv) { mv = s3;  mi = t + 768; }

        #pragma unroll
        for (int o = 16; o; o >>= 1) {
            float ov = __shfl_down_sync(0xffffffffu, mv, o);
            int   oi = __shfl_down_sync(0xffffffffu, mi, o);
            if (ov < mv || (ov == mv && oi < mi)) { mv = ov; mi = oi; }
        }
        if (lane == 0) { s_ra[wid] = mv; s_ri[wid] = mi; }
        __syncthreads();
        if (wid == 0) {
            float v = (lane < 8) ? s_ra[lane] : 3.4e38f;
            int  ii = (lane < 8) ? s_ri[lane] : 0x7fffffff;
            #pragma unroll
            for (int o = 4; o; o >>= 1) {
                float ov = __shfl_down_sync(0xffffffffu, v, o);
                int   oi = __shfl_down_sync(0xffffffffu, ii, o);
                if (ov < v || (ov == v && oi < ii)) { v = ov; ii = oi; }
            }
            if (lane == 0) { s_min = v; s_idx = ii; }
        }
        __syncthreads();
        const float smin = s_min;
        const int idx = s_idx;

        float d0 = s0 - smin, d1 = s1v - smin, d2 = s2 - smin, d3 = s3 - smin;
        float e0 = expf(-100.f * d0);
        float e1 = expf(-100.f * d1);
        float e2 = expf(-100.f * d2);
        float e3 = expf(-100.f * d3);
        float z  = e0 + e1 + e2 + e3;
        float s1sum = e0 * d0 + e1 * d1 + e2 * d2 + e3 * d3;

        float cv = CB[(size_t)idx * DIM + t];
        float xv = X[(size_t)n * DIM + t];
        out_q[(size_t)n * DIM + t] = cv;
        float df = cv - xv;
        float d2sum = df * df;

        #pragma unroll
        for (int o = 16; o; o >>= 1) {
            z     += __shfl_down_sync(0xffffffffu, z, o);
            s1sum += __shfl_down_sync(0xffffffffu, s1sum, o);
            d2sum += __shfl_down_sync(0xffffffffu, d2sum, o);
        }
        if (lane == 0) { s_ra[wid] = z; s_rb[wid] = s1sum; s_rc[wid] = d2sum; }
        __syncthreads();
        if (wid == 0) {
            float a = (lane < 8) ? s_ra[lane] : 0.f;
            float b = (lane < 8) ? s_rb[lane] : 0.f;
            float cc = (lane < 8) ? s_rc[lane] : 0.f;
            #pragma unroll
            for (int o = 4; o; o >>= 1) {
                a += __shfl_down_sync(0xffffffffu, a, o);
                b += __shfl_down_sync(0xffffffffu, b, o);
                cc += __shfl_down_sync(0xffffffffu, cc, o);
            }
            if (lane == 0) {
                s_Z = a;
                ent_sum += 100.f * (b / a) + logf(a);
                lat_sum += cc;
            }
        }
        __syncthreads();
        const float Z = s_Z;
        pacc0 += e0 / Z;
        pacc1 += e1 / Z;
        pacc2 += e2 / Z;
        pacc3 += e3 / Z;

        if (t == 0 && out_idx) out_idx[n] = (float)idx;
        __syncthreads();
    }

    atomicAdd(&g_probs[t],       pacc0);
    atomicAdd(&g_probs[t + 256], pacc1);
    atomicAdd(&g_probs[t + 512], pacc2);
    atomicAdd(&g_probs[t + 768], pacc3);
    if (t == 0) {
        atomicAdd(&g_scal[0], lat_sum);
        atomicAdd(&g_scal[1], ent_sum);
    }
}

// ---------------- finalize ----------------
__global__ void vq_finalize_kernel(float* __restrict__ out_loss) {
    __shared__ float warp_s[32];
    const int t = threadIdx.x;
    const int lane = t & 31;
    const int wid = t >> 5;

    float p = g_probs[t] * (1.0f / (float)N_ROWS);
    float contrib = -p * logf(p + 1e-5f);
    #pragma unroll
    for (int o = 16; o; o >>= 1) contrib += __shfl_down_sync(0xffffffffu, contrib, o);
    if (lane == 0) warp_s[wid] = contrib;
    __syncthreads();
    if (wid == 0) {
        float v = warp_s[lane];
        #pragma unroll
        for (int o = 16; o; o >>= 1) v += __shfl_down_sync(0xffffffffu, v, o);
        if (lane == 0 && out_loss) {
            float avg_entropy = v;
            float sample_entropy = g_scal[1] * (1.0f / (float)N_ROWS);
            float mean_lat = g_scal[0] * (1.0f / ((float)N_ROWS * (float)DIM));
            float ent_loss = sample_entropy - avg_entropy;
            *out_loss = 1.25f * mean_lat + 0.1f * ent_loss;
        }
    }
}

// ---------------- launch ----------------
extern "C" void kernel_launch(void* const* d_in, const int* in_sizes, int n_in,
                              void* d_out, int out_size) {
    const float* X  = (const float*)d_in[0];
    const float* CB = (const float*)d_in[1];
    float* out = (float*)d_out;

    float* out_q    = out;
    float* out_loss = (out_size >= N_ROWS * DIM + 1) ? (out + (size_t)N_ROWS * DIM) : nullptr;
    float* out_idx  = (out_size >= N_ROWS * DIM + 1 + N_ROWS) ? (out + (size_t)N_ROWS * DIM + 1) : nullptr;

    static int smem_set = 0;
    if (!smem_set) {
        cudaFuncSetAttribute(vq_mma_gemm, cudaFuncAttributeMaxDynamicSharedMemorySize,
                             GEMM_SMEM_BYTES);
        smem_set = 1;
    }

    vq_init_kernel<<<128, 256>>>(CB);
    vq_prep_a<<<(N_ROWS * DIM / 2) / 256, 256>>>(X);
    vq_prep_b<<<(KCODES * DIM / 2) / 256, 256>>>(CB);
    dim3 g(KCODES / BNg, N_ROWS / BMg);
    vq_mma_gemm<<<g, 512, GEMM_SMEM_BYTES>>>();
    vq_row_kernel<<<N_ROWS / ROWS_PER_BLOCK, 256>>>(X, CB, out_q, out_idx);
    vq_finalize_kernel<<<1, 1024>>>(out_loss);
}

// round 5
// speedup vs baseline: 2.4230x; 1.4173x over previous
#include <cuda_runtime.h>
#include <cuda_fp16.h>
#include <math.h>
#include <stdint.h>

#define N_ROWS 32768
#define DIM    256
#define KCODES 1024

// ---------------- device scratch ----------------
__device__ float  g_S[(size_t)N_ROWS * KCODES];    // s[n,k] = |c_k|^2 - 2 x.c   (134 MB)
__device__ __half g_Ah[(size_t)N_ROWS * 512];      // [Xhi | Xlo]        (32 MB)
__device__ __half g_Bh[(size_t)KCODES * 768];      // [Chi | Clo | Chi]  (1.5 MB)
__device__ float  g_c2[KCODES];
__device__ float  g_probs[KCODES];
__device__ float  g_scal[2];

// ---------------- PTX helpers (sm_100-safe, no 'a' features) ----------------
__device__ __forceinline__ uint32_t smem_u32(const void* p) {
    uint32_t a;
    asm("{ .reg .u64 t; cvta.to.shared.u64 t, %1; cvt.u32.u64 %0, t; }" : "=r"(a) : "l"(p));
    return a;
}
__device__ __forceinline__ void cp_async16(uint32_t dst, const void* src) {
    asm volatile("cp.async.cg.shared.global [%0], [%1], 16;" :: "r"(dst), "l"(src) : "memory");
}
__device__ __forceinline__ void cp_commit() {
    asm volatile("cp.async.commit_group;" ::: "memory");
}
template <int N>
__device__ __forceinline__ void cp_wait() {
    asm volatile("cp.async.wait_group %0;" :: "n"(N) : "memory");
}
__device__ __forceinline__ void ldsm4(uint32_t* r, uint32_t addr) {
    asm volatile("ldmatrix.sync.aligned.m8n8.x4.shared.b16 {%0,%1,%2,%3}, [%4];"
                 : "=r"(r[0]), "=r"(r[1]), "=r"(r[2]), "=r"(r[3]) : "r"(addr));
}
__device__ __forceinline__ void mma_f16(float* d, const uint32_t* a, uint32_t b0, uint32_t b1) {
    asm volatile(
        "mma.sync.aligned.m16n8k16.row.col.f32.f16.f16.f32 "
        "{%0,%1,%2,%3}, {%4,%5,%6,%7}, {%8,%9}, {%0,%1,%2,%3};"
        : "+f"(d[0]), "+f"(d[1]), "+f"(d[2]), "+f"(d[3])
        : "r"(a[0]), "r"(a[1]), "r"(a[2]), "r"(a[3]), "r"(b0), "r"(b1));
}

// ---------------- init: zero accumulators + codebook norms ----------------
__global__ void vq_init_kernel(const float* __restrict__ CB) {
    int gtid = blockIdx.x * blockDim.x + threadIdx.x;
    if (gtid < KCODES) g_probs[gtid] = 0.f;
    if (gtid < 2) g_scal[gtid] = 0.f;
    int wid = gtid >> 5;
    int lane = gtid & 31;
    if (wid < KCODES) {
        const float* c = CB + (size_t)wid * DIM;
        float s = 0.f;
        for (int i = lane; i < DIM; i += 32) { float v = c[i]; s += v * v; }
        #pragma unroll
        for (int o = 16; o; o >>= 1) s += __shfl_down_sync(0xffffffffu, s, o);
        if (lane == 0) g_c2[wid] = s;
    }
}

// ---------------- prep: fp16 hi/lo split ----------------
__global__ __launch_bounds__(256)
void vq_prep_a(const float* __restrict__ X) {
    int idx = blockIdx.x * blockDim.x + threadIdx.x;
    int i2 = idx * 2;
    int n = i2 >> 8;
    int d = i2 & 255;
    float2 x = *(const float2*)(X + i2);
    __half h0 = __float2half_rn(x.x);
    __half h1 = __float2half_rn(x.y);
    __half l0 = __float2half_rn(x.x - __half2float(h0));
    __half l1 = __float2half_rn(x.y - __half2float(h1));
    __half* row = g_Ah + (size_t)n * 512;
    *(half2*)(row + d)       = __halves2half2(h0, h1);
    *(half2*)(row + 256 + d) = __halves2half2(l0, l1);
}
__global__ __launch_bounds__(256)
void vq_prep_b(const float* __restrict__ CB) {
    int idx = blockIdx.x * blockDim.x + threadIdx.x;
    int i2 = idx * 2;
    int k = i2 >> 8;
    int d = i2 & 255;
    float2 x = *(const float2*)(CB + i2);
    __half h0 = __float2half_rn(x.x);
    __half h1 = __float2half_rn(x.y);
    __half l0 = __float2half_rn(x.x - __half2float(h0));
    __half l1 = __float2half_rn(x.y - __half2float(h1));
    __half* row = g_Bh + (size_t)k * 768;
    *(half2*)(row + d)       = __halves2half2(h0, h1);
    *(half2*)(row + 256 + d) = __halves2half2(l0, l1);
    *(half2*)(row + 512 + d) = __halves2half2(h0, h1);
}

// ---------------- fp16 mma.sync GEMM: s = c2[k] - 2*dot ----------------
// BM=128, BN=128, BK=32 halves, 256 threads (8 warps 4x2), warp tile 32x64.
// 24 chunks over K'=768: c<8: Ahi x Chi ; 8<=c<16: Ahi x Clo ; c>=16: Alo x Chi.
#define BMg 128
#define BNg 128
#define CHUNKS 24
#define STAGES 4
#define SH 40                                   // halves per smem row (80 B)
#define A_STAGE_H (BMg * SH)                    // 5120 halves (10240 B)
#define B_STAGE_H (BNg * SH)                    // 5120 halves
#define STAGE_H   (A_STAGE_H + B_STAGE_H)       // 10240 halves (20480 B)
#define GEMM_SMEM_BYTES (STAGES * STAGE_H * 2 + BNg * 4)   // 81920 + 512

__global__ __launch_bounds__(256, 2)
void vq_mma_gemm() {
    extern __shared__ __align__(16) __half smem[];
    float* s_c2 = (float*)(smem + STAGES * STAGE_H);

    const int tid  = threadIdx.x;
    const int lane = tid & 31;
    const int wid  = tid >> 5;
    const int warp_row = wid & 3;     // 0..3
    const int warp_col = wid >> 2;    // 0..1
    const int bn = blockIdx.x;        // 0..7
    const int bm = blockIdx.y;        // 0..255

    if (tid < BNg) s_c2[tid] = g_c2[bn * BNg + tid];

    const __half* Abase = g_Ah + (size_t)(bm * BMg) * 512;
    const __half* Bbase = g_Bh + (size_t)(bn * BNg) * 768;
    const uint32_t sbase = smem_u32(smem);

    auto load_chunk = [&](int c) {
        const int stage = c % STAGES;
        const uint32_t dA = sbase + stage * (STAGE_H * 2);
        const uint32_t dB = dA + A_STAGE_H * 2;
        const int phase = c >> 3;
        const int acol = (phase == 2 ? 256 : 0) + (c & 7) * 32;
        const int bcol = c * 32;
        #pragma unroll
        for (int i = 0; i < 2; i++) {   // A: 128 rows x 64B = 512 x 16B
            int idx = tid + i * 256;
            int row = idx >> 2, c16 = idx & 3;
            cp_async16(dA + row * (SH * 2) + c16 * 16,
                       Abase + (size_t)row * 512 + acol + c16 * 8);
        }
        #pragma unroll
        for (int i = 0; i < 2; i++) {   // B: 128 rows x 64B
            int idx = tid + i * 256;
            int row = idx >> 2, c16 = idx & 3;
            cp_async16(dB + row * (SH * 2) + c16 * 16,
                       Bbase + (size_t)row * 768 + bcol + c16 * 8);
        }
        cp_commit();
    };

    float acc[2][8][4];
    #pragma unroll
    for (int mt = 0; mt < 2; mt++)
        #pragma unroll
        for (int nn = 0; nn < 8; nn++)
            #pragma unroll
            for (int j = 0; j < 4; j++) acc[mt][nn][j] = 0.f;

    load_chunk(0);
    load_chunk(1);
    load_chunk(2);

    const int grp = lane >> 3;
    const int rin = lane & 7;

    for (int c = 0; c < CHUNKS; c++) {
        cp_wait<2>();          // group c has landed
        __syncthreads();       // all warps done computing c-1 (stage (c+3)%4 is free)
        if (c + 3 < CHUNKS) load_chunk(c + 3);

        const int stage = c % STAGES;
        const uint32_t aS = sbase + stage * (STAGE_H * 2);
        const uint32_t bS = aS + A_STAGE_H * 2;

        #pragma unroll
        for (int ks = 0; ks < 2; ks++) {
            const uint32_t kbyte = ks * 32;
            uint32_t a[2][4];
            #pragma unroll
            for (int mt = 0; mt < 2; mt++) {
                int arow = warp_row * 32 + mt * 16 + ((grp & 1) << 3) + rin;
                ldsm4(a[mt], aS + arow * (SH * 2) + kbyte + (grp >> 1) * 16);
            }
            uint32_t b[8][2];
            #pragma unroll
            for (int np = 0; np < 4; np++) {
                int brow = warp_col * 64 + np * 16 + ((grp >> 1) << 3) + rin;
                uint32_t b4[4];
                ldsm4(b4, bS + brow * (SH * 2) + kbyte + (grp & 1) * 16);
                b[np * 2][0]     = b4[0]; b[np * 2][1]     = b4[1];
                b[np * 2 + 1][0] = b4[2]; b[np * 2 + 1][1] = b4[3];
            }
            #pragma unroll
            for (int nn = 0; nn < 8; nn++) {
                mma_f16(acc[0][nn], a[0], b[nn][0], b[nn][1]);
                mma_f16(acc[1][nn], a[1], b[nn][0], b[nn][1]);
            }
        }
    }

    // epilogue: s = c2[k] - 2*acc
    const int r4 = lane >> 2;
    const int c4 = lane & 3;
    #pragma unroll
    for (int mt = 0; mt < 2; mt++) {
        int row0 = bm * BMg + warp_row * 32 + mt * 16 + r4;
        #pragma unroll
        for (int nn = 0; nn < 8; nn++) {
            int ncl = warp_col * 64 + nn * 8 + c4 * 2;
            int col = bn * BNg + ncl;
            float2 v0, v1;
            v0.x = s_c2[ncl]     - 2.f * acc[mt][nn][0];
            v0.y = s_c2[ncl + 1] - 2.f * acc[mt][nn][1];
            v1.x = s_c2[ncl]     - 2.f * acc[mt][nn][2];
            v1.y = s_c2[ncl + 1] - 2.f * acc[mt][nn][3];
            *(float2*)(g_S + (size_t)row0 * KCODES + col)       = v0;
            *(float2*)(g_S + (size_t)(row0 + 8) * KCODES + col) = v1;
        }
    }
}

// ---------------- warp-per-row: argmin, softmax, gather, loss partials ----------------
// 256 blocks x 8 warps, 16 rows per warp; no __syncthreads in the hot loop.
#define RW_BLOCKS 256
#define RW_WARPS  8
#define RW_ROWS   16    // rows per warp

__global__ __launch_bounds__(256)
void vq_row_kernel(const float* __restrict__ X, const float* __restrict__ CB,
                   float* __restrict__ out_q, float* __restrict__ out_idx) {
    __shared__ float s_probs[KCODES];

    const int t = threadIdx.x;
    const int lane = t & 31;
    const int wid = t >> 5;

    #pragma unroll
    for (int i = t; i < KCODES; i += 256) s_probs[i] = 0.f;
    __syncthreads();

    float pacc[32];
    #pragma unroll
    for (int i = 0; i < 32; i++) pacc[i] = 0.f;
    float ent_sum = 0.f, lat_acc = 0.f;

    const int warp_g = blockIdx.x * RW_WARPS + wid;   // 0..2047

    for (int r = 0; r < RW_ROWS; r++) {
        const int n = warp_g * RW_ROWS + r;
        const float* srow = g_S + (size_t)n * KCODES;

        // load 32 distances per lane: code id = m*128 + lane*4 + j
        float4 sv[8];
        #pragma unroll
        for (int m = 0; m < 8; m++)
            sv[m] = *(const float4*)(srow + m * 128 + lane * 4);

        // lane-local argmin (ascending index order -> earliest wins ties)
        float mv = sv[0].x; int mi = lane * 4;
        #pragma unroll
        for (int m = 0; m < 8; m++) {
            int base = m * 128 + lane * 4;
            float v0 = sv[m].x, v1 = sv[m].y, v2 = sv[m].z, v3 = sv[m].w;
            if (v0 < mv) { mv = v0; mi = base; }
            if (v1 < mv) { mv = v1; mi = base + 1; }
            if (v2 < mv) { mv = v2; mi = base + 2; }
            if (v3 < mv) { mv = v3; mi = base + 3; }
        }
        // warp butterfly argmin (all lanes get result)
        #pragma unroll
        for (int o = 16; o; o >>= 1) {
            float ov = __shfl_xor_sync(0xffffffffu, mv, o);
            int   oi = __shfl_xor_sync(0xffffffffu, mi, o);
            if (ov < mv || (ov == mv && oi < mi)) { mv = ov; mi = oi; }
        }

        // softmax stats
        float e[32];
        float z = 0.f, s1 = 0.f;
        #pragma unroll
        for (int m = 0; m < 8; m++) {
            float d0 = sv[m].x - mv, d1 = sv[m].y - mv;
            float d2 = sv[m].z - mv, d3 = sv[m].w - mv;
            float e0 = expf(-100.f * d0);
            float e1 = expf(-100.f * d1);
            float e2 = expf(-100.f * d2);
            float e3 = expf(-100.f * d3);
            e[m * 4 + 0] = e0; e[m * 4 + 1] = e1; e[m * 4 + 2] = e2; e[m * 4 + 3] = e3;
            z  += e0 + e1 + e2 + e3;
            s1 += e0 * d0 + e1 * d1 + e2 * d2 + e3 * d3;
        }
        #pragma unroll
        for (int o = 16; o; o >>= 1) {
            z  += __shfl_xor_sync(0xffffffffu, z, o);
            s1 += __shfl_xor_sync(0xffffffffu, s1, o);
        }
        const float invZ = 1.f / z;
        #pragma unroll
        for (int i = 0; i < 32; i++) pacc[i] += e[i] * invZ;
        if (lane == 0) ent_sum += 100.f * (s1 * invZ) + logf(z);

        // gather quantized row + latent loss + outputs
        float lsum = 0.f;
        #pragma unroll
        for (int m = 0; m < 2; m++) {
            int d = m * 128 + lane * 4;
            float4 cv = *(const float4*)(CB + (size_t)mi * DIM + d);
            float4 xv = *(const float4*)(X  + (size_t)n  * DIM + d);
            *(float4*)(out_q + (size_t)n * DIM + d) = cv;
            float f0 = cv.x - xv.x, f1 = cv.y - xv.y, f2 = cv.z - xv.z, f3 = cv.w - xv.w;
            lsum += f0 * f0 + f1 * f1 + f2 * f2 + f3 * f3;
        }
        #pragma unroll
        for (int o = 16; o; o >>= 1) lsum += __shfl_down_sync(0xffffffffu, lsum, o);
        if (lane == 0) {
            lat_acc += lsum;
            if (out_idx) out_idx[n] = (float)mi;
        }
    }

    // fold per-lane prob partials through shared, then global atomics
    #pragma unroll
    for (int m = 0; m < 8; m++) {
        int base = m * 128 + lane * 4;
        atomicAdd(&s_probs[base + 0], pacc[m * 4 + 0]);
        atomicAdd(&s_probs[base + 1], pacc[m * 4 + 1]);
        atomicAdd(&s_probs[base + 2], pacc[m * 4 + 2]);
        atomicAdd(&s_probs[base + 3], pacc[m * 4 + 3]);
    }
    __syncthreads();
    #pragma unroll
    for (int i = t; i < KCODES; i += 256) atomicAdd(&g_probs[i], s_probs[i]);
    if (lane == 0) {
        atomicAdd(&g_scal[0], lat_acc);
        atomicAdd(&g_scal[1], ent_sum);
    }
}

// ---------------- finalize ----------------
__global__ void vq_finalize_kernel(float* __restrict__ out_loss) {
    __shared__ float warp_s[32];
    const int t = threadIdx.x;
    const int lane = t & 31;
    const int wid = t >> 5;

    float p = g_probs[t] * (1.0f / (float)N_ROWS);
    float contrib = -p * logf(p + 1e-5f);
    #pragma unroll
    for (int o = 16; o; o >>= 1) contrib += __shfl_down_sync(0xffffffffu, contrib, o);
    if (lane == 0) warp_s[wid] = contrib;
    __syncthreads();
    if (wid == 0) {
        float v = warp_s[lane];
        #pragma unroll
        for (int o = 16; o; o >>= 1) v += __shfl_down_sync(0xffffffffu, v, o);
        if (lane == 0 && out_loss) {
            float avg_entropy = v;
            float sample_entropy = g_scal[1] * (1.0f / (float)N_ROWS);
            float mean_lat = g_scal[0] * (1.0f / ((float)N_ROWS * (float)DIM));
            float ent_loss = sample_entropy - avg_entropy;
            *out_loss = 1.25f * mean_lat + 0.1f * ent_loss;
        }
    }
}

// ---------------- launch ----------------
extern "C" void kernel_launch(void* const* d_in, const int* in_sizes, int n_in,
                              void* d_out, int out_size) {
    const float* X  = (const float*)d_in[0];
    const float* CB = (const float*)d_in[1];
    float* out = (float*)d_out;

    float* out_q    = out;
    float* out_loss = (out_size >= N_ROWS * DIM + 1) ? (out + (size_t)N_ROWS * DIM) : nullptr;
    float* out_idx  = (out_size >= N_ROWS * DIM + 1 + N_ROWS) ? (out + (size_t)N_ROWS * DIM + 1) : nullptr;

    static int smem_set = 0;
    if (!smem_set) {
        cudaFuncSetAttribute(vq_mma_gemm, cudaFuncAttributeMaxDynamicSharedMemorySize,
                             GEMM_SMEM_BYTES);
        smem_set = 1;
    }

    vq_init_kernel<<<128, 256>>>(CB);
    vq_prep_a<<<(N_ROWS * DIM / 2) / 256, 256>>>(X);
    vq_prep_b<<<(KCODES * DIM / 2) / 256, 256>>>(CB);
    dim3 g(KCODES / BNg, N_ROWS / BMg);
    vq_mma_gemm<<<g, 256, GEMM_SMEM_BYTES>>>();
    vq_row_kernel<<<RW_BLOCKS, 256>>>(X, CB, out_q, out_idx);
    vq_finalize_kernel<<<1, 1024>>>(out_loss);
}

// round 8
// speedup vs baseline: 3.9966x; 1.6495x over previous
#include <cuda_runtime.h>
#include <cuda_fp16.h>
#include <math.h>
#include <stdint.h>

#define N_ROWS 32768
#define DIM    256
#define KCODES 1024
#define MARGIN 1.0f

// ---------------- device scratch ----------------
__device__ float  g_S[(size_t)N_ROWS * KCODES];    // approx s[n,k] = |c|^2 - 2 xh.ch  (134 MB)
__device__ __half g_Ah[(size_t)N_ROWS * DIM];      // X hi  (16 MB)
__device__ __half g_Bh[(size_t)KCODES * DIM];      // CB hi (0.5 MB)
__device__ float  g_c2[KCODES];
__device__ float  g_probs[KCODES];
__device__ float  g_scal[2];

// ---------------- PTX helpers (sm_100-safe, no 'a' features) ----------------
__device__ __forceinline__ uint32_t smem_u32(const void* p) {
    uint32_t a;
    asm("{ .reg .u64 t; cvta.to.shared.u64 t, %1; cvt.u32.u64 %0, t; }" : "=r"(a) : "l"(p));
    return a;
}
__device__ __forceinline__ void cp_async16(uint32_t dst, const void* src) {
    asm volatile("cp.async.cg.shared.global [%0], [%1], 16;" :: "r"(dst), "l"(src) : "memory");
}
__device__ __forceinline__ void cp_commit() {
    asm volatile("cp.async.commit_group;" ::: "memory");
}
template <int N>
__device__ __forceinline__ void cp_wait() {
    asm volatile("cp.async.wait_group %0;" :: "n"(N) : "memory");
}
__device__ __forceinline__ void ldsm4(uint32_t* r, uint32_t addr) {
    asm volatile("ldmatrix.sync.aligned.m8n8.x4.shared.b16 {%0,%1,%2,%3}, [%4];"
                 : "=r"(r[0]), "=r"(r[1]), "=r"(r[2]), "=r"(r[3]) : "r"(addr));
}
__device__ __forceinline__ void mma_f16(float* d, const uint32_t* a, uint32_t b0, uint32_t b1) {
    asm volatile(
        "mma.sync.aligned.m16n8k16.row.col.f32.f16.f16.f32 "
        "{%0,%1,%2,%3}, {%4,%5,%6,%7}, {%8,%9}, {%0,%1,%2,%3};"
        : "+f"(d[0]), "+f"(d[1]), "+f"(d[2]), "+f"(d[3])
        : "r"(a[0]), "r"(a[1]), "r"(a[2]), "r"(a[3]), "r"(b0), "r"(b1));
}

// ---------------- init: zero accumulators + codebook norms ----------------
__global__ void vq_init_kernel(const float* __restrict__ CB) {
    int gtid = blockIdx.x * blockDim.x + threadIdx.x;
    if (gtid < KCODES) g_probs[gtid] = 0.f;
    if (gtid < 2) g_scal[gtid] = 0.f;
    int wid = gtid >> 5;
    int lane = gtid & 31;
    if (wid < KCODES) {
        const float* c = CB + (size_t)wid * DIM;
        float s = 0.f;
        for (int i = lane; i < DIM; i += 32) { float v = c[i]; s += v * v; }
        #pragma unroll
        for (int o = 16; o; o >>= 1) s += __shfl_down_sync(0xffffffffu, s, o);
        if (lane == 0) g_c2[wid] = s;
    }
}

// ---------------- prep: fp16 hi conversion ----------------
__global__ __launch_bounds__(256)
void vq_prep_a(const float* __restrict__ X) {
    int idx = blockIdx.x * blockDim.x + threadIdx.x;
    int i2 = idx * 2;
    float2 x = *(const float2*)(X + i2);
    *(half2*)(g_Ah + i2) = __halves2half2(__float2half_rn(x.x), __float2half_rn(x.y));
}
__global__ __launch_bounds__(256)
void vq_prep_b(const float* __restrict__ CB) {
    int idx = blockIdx.x * blockDim.x + threadIdx.x;
    int i2 = idx * 2;
    float2 x = *(const float2*)(CB + i2);
    *(half2*)(g_Bh + i2) = __halves2half2(__float2half_rn(x.x), __float2half_rn(x.y));
}

// ---------------- fp16 mma.sync GEMM (hi only): s = c2[k] - 2*dot ----------------
// BM=128, BN=256, BK=32 halves, 512 threads (16 warps 4x4), warp tile 32x64, 8 chunks.
#define BMg 128
#define BNg 256
#define CHUNKS 8
#define STAGES 3
#define SH 40                                   // halves per smem row (80 B)
#define A_STAGE_H (BMg * SH)                    // 5120 halves
#define B_STAGE_H (BNg * SH)                    // 10240 halves
#define STAGE_H   (A_STAGE_H + B_STAGE_H)       // 15360 halves (30720 B)
#define GEMM_SMEM_BYTES (STAGES * STAGE_H * 2 + BNg * 4)

__global__ __launch_bounds__(512, 1)
void vq_mma_gemm() {
    extern __shared__ __align__(16) __half smem[];
    float* s_c2 = (float*)(smem + STAGES * STAGE_H);

    const int tid  = threadIdx.x;
    const int lane = tid & 31;
    const int wid  = tid >> 5;
    const int warp_row = wid & 3;
    const int warp_col = wid >> 2;
    const int bn = blockIdx.x;      // 0..3
    const int bm = blockIdx.y;      // 0..255

    if (tid < BNg) s_c2[tid] = g_c2[bn * BNg + tid];

    const __half* Abase = g_Ah + (size_t)(bm * BMg) * DIM;
    const __half* Bbase = g_Bh + (size_t)(bn * BNg) * DIM;
    const uint32_t sbase = smem_u32(smem);

    auto load_chunk = [&](int c) {
        const int stage = c % STAGES;
        const uint32_t dA = sbase + stage * (STAGE_H * 2);
        const uint32_t dB = dA + A_STAGE_H * 2;
        const int col = c * 32;
        {   // A: 128 rows x 64 B = 512 x 16B
            int row = tid >> 2, c16 = tid & 3;
            cp_async16(dA + row * (SH * 2) + c16 * 16,
                       Abase + (size_t)row * DIM + col + c16 * 8);
        }
        #pragma unroll
        for (int i = 0; i < 2; i++) {   // B: 256 rows x 64 B
            int idx = tid + i * 512;
            int row = idx >> 2, c16 = idx & 3;
            cp_async16(dB + row * (SH * 2) + c16 * 16,
                       Bbase + (size_t)row * DIM + col + c16 * 8);
        }
        cp_commit();
    };

    float acc[2][8][4];
    #pragma unroll
    for (int mt = 0; mt < 2; mt++)
        #pragma unroll
        for (int nn = 0; nn < 8; nn++)
            #pragma unroll
            for (int j = 0; j < 4; j++) acc[mt][nn][j] = 0.f;

    load_chunk(0);
    load_chunk(1);

    const int grp = lane >> 3;
    const int rin = lane & 7;

    for (int c = 0; c < CHUNKS; c++) {
        cp_wait<1>();
        __syncthreads();
        if (c + 2 < CHUNKS) load_chunk(c + 2);

        const int stage = c % STAGES;
        const uint32_t aS = sbase + stage * (STAGE_H * 2);
        const uint32_t bS = aS + A_STAGE_H * 2;

        #pragma unroll
        for (int ks = 0; ks < 2; ks++) {
            const uint32_t kbyte = ks * 32;
            uint32_t a[2][4];
            #pragma unroll
            for (int mt = 0; mt < 2; mt++) {
                int arow = warp_row * 32 + mt * 16 + ((grp & 1) << 3) + rin;
                ldsm4(a[mt], aS + arow * (SH * 2) + kbyte + (grp >> 1) * 16);
            }
            uint32_t b[8][2];
            #pragma unroll
            for (int np = 0; np < 4; np++) {
                int brow = warp_col * 64 + np * 16 + ((grp >> 1) << 3) + rin;
                uint32_t b4[4];
                ldsm4(b4, bS + brow * (SH * 2) + kbyte + (grp & 1) * 16);
                b[np * 2][0]     = b4[0]; b[np * 2][1]     = b4[1];
                b[np * 2 + 1][0] = b4[2]; b[np * 2 + 1][1] = b4[3];
            }
            #pragma unroll
            for (int nn = 0; nn < 8; nn++) {
                mma_f16(acc[0][nn], a[0], b[nn][0], b[nn][1]);
                mma_f16(acc[1][nn], a[1], b[nn][0], b[nn][1]);
            }
        }
        __syncthreads();
    }

    const int r4 = lane >> 2;
    const int c4 = lane & 3;
    #pragma unroll
    for (int mt = 0; mt < 2; mt++) {
        int row0 = bm * BMg + warp_row * 32 + mt * 16 + r4;
        #pragma unroll
        for (int nn = 0; nn < 8; nn++) {
            int ncl = warp_col * 64 + nn * 8 + c4 * 2;
            int col = bn * BNg + ncl;
            float2 v0, v1;
            v0.x = s_c2[ncl]     - 2.f * acc[mt][nn][0];
            v0.y = s_c2[ncl + 1] - 2.f * acc[mt][nn][1];
            v1.x = s_c2[ncl]     - 2.f * acc[mt][nn][2];
            v1.y = s_c2[ncl + 1] - 2.f * acc[mt][nn][3];
            *(float2*)(g_S + (size_t)row0 * KCODES + col)       = v0;
            *(float2*)(g_S + (size_t)(row0 + 8) * KCODES + col) = v1;
        }
    }
}

// ---------------- warp-per-row: screen + exact refine + softmax + gather ----------------
// s-space convention: s = ||c||^2 - 2 x.c  (= ||x-c||^2 - ||x||^2). Refined entries
// store d_exact - x2 so all values stay comparable.
#define RW_BLOCKS 256
#define RW_WARPS  8
#define RW_ROWS   16

__global__ __launch_bounds__(256)
void vq_row_kernel(const float* __restrict__ X, const float* __restrict__ CB,
                   float* __restrict__ out_q, float* __restrict__ out_idx) {
    __shared__ float s_probs[KCODES];

    const int t = threadIdx.x;
    const int lane = t & 31;
    const int wid = t >> 5;

    #pragma unroll
    for (int i = t; i < KCODES; i += 256) s_probs[i] = 0.f;
    __syncthreads();

    float pacc[32];
    #pragma unroll
    for (int i = 0; i < 32; i++) pacc[i] = 0.f;
    float ent_sum = 0.f, lat_acc = 0.f;

    const int warp_g = blockIdx.x * RW_WARPS + wid;

    for (int r = 0; r < RW_ROWS; r++) {
        const int n = warp_g * RW_ROWS + r;
        const float* srow = g_S + (size_t)n * KCODES;

        // approx distances: code id = m*128 + lane*4 + j
        float4 sv[8];
        #pragma unroll
        for (int m = 0; m < 8; m++)
            sv[m] = *(const float4*)(srow + m * 128 + lane * 4);

        // preload x row slice (8 floats per lane) + row norm x2
        const float* xrow = X + (size_t)n * DIM + lane * 8;
        const float4 xr0 = *(const float4*)(xrow);
        const float4 xr1 = *(const float4*)(xrow + 4);
        float x2 = xr0.x*xr0.x + xr0.y*xr0.y + xr0.z*xr0.z + xr0.w*xr0.w
                 + xr1.x*xr1.x + xr1.y*xr1.y + xr1.z*xr1.z + xr1.w*xr1.w;
        #pragma unroll
        for (int o = 16; o; o >>= 1) x2 += __shfl_xor_sync(0xffffffffu, x2, o);

        // approx min value (warp)
        float mv = fminf(fminf(sv[0].x, sv[0].y), fminf(sv[0].z, sv[0].w));
        #pragma unroll
        for (int m = 1; m < 8; m++)
            mv = fminf(mv, fminf(fminf(sv[m].x, sv[m].y), fminf(sv[m].z, sv[m].w)));
        #pragma unroll
        for (int o = 16; o; o >>= 1)
            mv = fminf(mv, __shfl_xor_sync(0xffffffffu, mv, o));
        const float thr = mv + MARGIN;

        // candidate bitmask over my 32 slots
        unsigned pend = 0;
        #pragma unroll
        for (int m = 0; m < 8; m++) {
            if (sv[m].x < thr) pend |= 1u << (m * 4 + 0);
            if (sv[m].y < thr) pend |= 1u << (m * 4 + 1);
            if (sv[m].z < thr) pend |= 1u << (m * 4 + 2);
            if (sv[m].w < thr) pend |= 1u << (m * 4 + 3);
        }

        // refine each candidate with an exact fp32 warp dot; store d_exact - x2
        while (true) {
            unsigned anyb = __ballot_sync(0xffffffffu, pend != 0);
            if (!anyb) break;
            int src = __ffs(anyb) - 1;
            unsigned pb = __shfl_sync(0xffffffffu, pend, src);
            int slot = __ffs(pb) - 1;
            if (lane == src) pend &= pend - 1;
            int k = (slot >> 2) * 128 + src * 4 + (slot & 3);

            const float* crow = CB + (size_t)k * DIM + lane * 8;
            float4 c0 = *(const float4*)(crow);
            float4 c1 = *(const float4*)(crow + 4);
            float f0 = xr0.x - c0.x, f1 = xr0.y - c0.y, f2 = xr0.z - c0.z, f3 = xr0.w - c0.w;
            float f4 = xr1.x - c1.x, f5 = xr1.y - c1.y, f6 = xr1.z - c1.z, f7 = xr1.w - c1.w;
            float d = f0*f0 + f1*f1 + f2*f2 + f3*f3 + f4*f4 + f5*f5 + f6*f6 + f7*f7;
            #pragma unroll
            for (int o = 16; o; o >>= 1) d += __shfl_xor_sync(0xffffffffu, d, o);

            if (lane == src) {
                float snew = d - x2;     // back to s-space
                int m = slot >> 2, j = slot & 3;
                #pragma unroll
                for (int mm = 0; mm < 8; mm++) if (mm == m) {
                    if (j == 0) sv[mm].x = snew;
                    else if (j == 1) sv[mm].y = snew;
                    else if (j == 2) sv[mm].z = snew;
                    else sv[mm].w = snew;
                }
            }
        }

        // exact argmin in s-space (earliest index wins ties)
        float bmv = sv[0].x; int bmi = lane * 4;
        #pragma unroll
        for (int m = 0; m < 8; m++) {
            int base = m * 128 + lane * 4;
            if (sv[m].x < bmv) { bmv = sv[m].x; bmi = base; }
            if (sv[m].y < bmv) { bmv = sv[m].y; bmi = base + 1; }
            if (sv[m].z < bmv) { bmv = sv[m].z; bmi = base + 2; }
            if (sv[m].w < bmv) { bmv = sv[m].w; bmi = base + 3; }
        }
        #pragma unroll
        for (int o = 16; o; o >>= 1) {
            float ov = __shfl_xor_sync(0xffffffffu, bmv, o);
            int   oi = __shfl_xor_sync(0xffffffffu, bmi, o);
            if (ov < bmv || (ov == bmv && oi < bmi)) { bmv = ov; bmi = oi; }
        }

        // softmax stats (exact near min; far values underflow to 0)
        float e[32];
        float z = 0.f, s1 = 0.f;
        #pragma unroll
        for (int m = 0; m < 8; m++) {
            float d0 = sv[m].x - bmv, d1 = sv[m].y - bmv;
            float d2 = sv[m].z - bmv, d3 = sv[m].w - bmv;
            float e0 = expf(-100.f * d0);
            float e1 = expf(-100.f * d1);
            float e2 = expf(-100.f * d2);
            float e3 = expf(-100.f * d3);
            e[m * 4 + 0] = e0; e[m * 4 + 1] = e1; e[m * 4 + 2] = e2; e[m * 4 + 3] = e3;
            z  += e0 + e1 + e2 + e3;
            s1 += e0 * d0 + e1 * d1 + e2 * d2 + e3 * d3;
        }
        #pragma unroll
        for (int o = 16; o; o >>= 1) {
            z  += __shfl_xor_sync(0xffffffffu, z, o);
            s1 += __shfl_xor_sync(0xffffffffu, s1, o);
        }
        const float invZ = 1.f / z;
        #pragma unroll
        for (int i = 0; i < 32; i++) pacc[i] += e[i] * invZ;

        // gather quantized row; latent loss = winner's exact distance (= bmv + x2)
        const float* crow = CB + (size_t)bmi * DIM + lane * 8;
        float4 q0 = *(const float4*)(crow);
        float4 q1 = *(const float4*)(crow + 4);
        *(float4*)(out_q + (size_t)n * DIM + lane * 8)     = q0;
        *(float4*)(out_q + (size_t)n * DIM + lane * 8 + 4) = q1;

        if (lane == 0) {
            ent_sum += 100.f * (s1 * invZ) + logf(z);
            lat_acc += bmv + x2;
            if (out_idx) out_idx[n] = (float)bmi;
        }
    }

    #pragma unroll
    for (int m = 0; m < 8; m++) {
        int base = m * 128 + lane * 4;
        atomicAdd(&s_probs[base + 0], pacc[m * 4 + 0]);
        atomicAdd(&s_probs[base + 1], pacc[m * 4 + 1]);
        atomicAdd(&s_probs[base + 2], pacc[m * 4 + 2]);
        atomicAdd(&s_probs[base + 3], pacc[m * 4 + 3]);
    }
    __syncthreads();
    #pragma unroll
    for (int i = t; i < KCODES; i += 256) atomicAdd(&g_probs[i], s_probs[i]);
    if (lane == 0) {
        atomicAdd(&g_scal[0], lat_acc);
        atomicAdd(&g_scal[1], ent_sum);
    }
}

// ---------------- finalize ----------------
__global__ void vq_finalize_kernel(float* __restrict__ out_loss) {
    __shared__ float warp_s[32];
    const int t = threadIdx.x;
    const int lane = t & 31;
    const int wid = t >> 5;

    float p = g_probs[t] * (1.0f / (float)N_ROWS);
    float contrib = -p * logf(p + 1e-5f);
    #pragma unroll
    for (int o = 16; o; o >>= 1) contrib += __shfl_down_sync(0xffffffffu, contrib, o);
    if (lane == 0) warp_s[wid] = contrib;
    __syncthreads();
    if (wid == 0) {
        float v = warp_s[lane];
        #pragma unroll
        for (int o = 16; o; o >>= 1) v += __shfl_down_sync(0xffffffffu, v, o);
        if (lane == 0 && out_loss) {
            float avg_entropy = v;
            float sample_entropy = g_scal[1] * (1.0f / (float)N_ROWS);
            float mean_lat = g_scal[0] * (1.0f / ((float)N_ROWS * (float)DIM));
            float ent_loss = sample_entropy - avg_entropy;
            *out_loss = 1.25f * mean_lat + 0.1f * ent_loss;
        }
    }
}

// ---------------- launch ----------------
extern "C" void kernel_launch(void* const* d_in, const int* in_sizes, int n_in,
                              void* d_out, int out_size) {
    const float* X  = (const float*)d_in[0];
    const float* CB = (const float*)d_in[1];
    float* out = (float*)d_out;

    float* out_q    = out;
    float* out_loss = (out_size >= N_ROWS * DIM + 1) ? (out + (size_t)N_ROWS * DIM) : nullptr;
    float* out_idx  = (out_size >= N_ROWS * DIM + 1 + N_ROWS) ? (out + (size_t)N_ROWS * DIM + 1) : nullptr;

    static int smem_set = 0;
    if (!smem_set) {
        cudaFuncSetAttribute(vq_mma_gemm, cudaFuncAttributeMaxDynamicSharedMemorySize,
                             GEMM_SMEM_BYTES);
        smem_set = 1;
    }

    vq_init_kernel<<<128, 256>>>(CB);
    vq_prep_a<<<(N_ROWS * DIM / 2) / 256, 256>>>(X);
    vq_prep_b<<<(KCODES * DIM / 2) / 256, 256>>>(CB);
    dim3 g(KCODES / BNg, N_ROWS / BMg);
    vq_mma_gemm<<<g, 512, GEMM_SMEM_BYTES>>>();
    vq_row_kernel<<<RW_BLOCKS, 256>>>(X, CB, out_q, out_idx);
    vq_finalize_kernel<<<1, 1024>>>(out_loss);
}

// round 9
// speedup vs baseline: 4.1411x; 1.0362x over previous
#include <cuda_runtime.h>
#include <cuda_fp16.h>
#include <math.h>
#include <stdint.h>

#define N_ROWS 32768
#define DIM    256
#define KCODES 1024
#define MARGIN 1.0f

// ---------------- device scratch ----------------
__device__ __half g_Sh[(size_t)N_ROWS * KCODES];   // approx s[n,k] = |c|^2 - 2 xh.ch (67 MB, fp16)
__device__ __half g_Ah[(size_t)N_ROWS * DIM];      // X hi  (16 MB)
__device__ __half g_Bh[(size_t)KCODES * DIM];      // CB hi (0.5 MB)
__device__ float  g_c2[KCODES];
__device__ float  g_probs[KCODES];
__device__ float  g_scal[2];

// ---------------- PTX helpers (sm_100-safe, no 'a' features) ----------------
__device__ __forceinline__ uint32_t smem_u32(const void* p) {
    uint32_t a;
    asm("{ .reg .u64 t; cvta.to.shared.u64 t, %1; cvt.u32.u64 %0, t; }" : "=r"(a) : "l"(p));
    return a;
}
__device__ __forceinline__ void cp_async16(uint32_t dst, const void* src) {
    asm volatile("cp.async.cg.shared.global [%0], [%1], 16;" :: "r"(dst), "l"(src) : "memory");
}
__device__ __forceinline__ void cp_commit() {
    asm volatile("cp.async.commit_group;" ::: "memory");
}
template <int N>
__device__ __forceinline__ void cp_wait() {
    asm volatile("cp.async.wait_group %0;" :: "n"(N) : "memory");
}
__device__ __forceinline__ void ldsm4(uint32_t* r, uint32_t addr) {
    asm volatile("ldmatrix.sync.aligned.m8n8.x4.shared.b16 {%0,%1,%2,%3}, [%4];"
                 : "=r"(r[0]), "=r"(r[1]), "=r"(r[2]), "=r"(r[3]) : "r"(addr));
}
__device__ __forceinline__ void mma_f16(float* d, const uint32_t* a, uint32_t b0, uint32_t b1) {
    asm volatile(
        "mma.sync.aligned.m16n8k16.row.col.f32.f16.f16.f32 "
        "{%0,%1,%2,%3}, {%4,%5,%6,%7}, {%8,%9}, {%0,%1,%2,%3};"
        : "+f"(d[0]), "+f"(d[1]), "+f"(d[2]), "+f"(d[3])
        : "r"(a[0]), "r"(a[1]), "r"(a[2]), "r"(a[3]), "r"(b0), "r"(b1));
}

// ---------------- init: zero accumulators + codebook norms ----------------
__global__ void vq_init_kernel(const float* __restrict__ CB) {
    int gtid = blockIdx.x * blockDim.x + threadIdx.x;
    if (gtid < KCODES) g_probs[gtid] = 0.f;
    if (gtid < 2) g_scal[gtid] = 0.f;
    int wid = gtid >> 5;
    int lane = gtid & 31;
    if (wid < KCODES) {
        const float* c = CB + (size_t)wid * DIM;
        float s = 0.f;
        for (int i = lane; i < DIM; i += 32) { float v = c[i]; s += v * v; }
        #pragma unroll
        for (int o = 16; o; o >>= 1) s += __shfl_down_sync(0xffffffffu, s, o);
        if (lane == 0) g_c2[wid] = s;
    }
}

// ---------------- prep: fp16 hi conversion ----------------
__global__ __launch_bounds__(256)
void vq_prep_a(const float* __restrict__ X) {
    int idx = blockIdx.x * blockDim.x + threadIdx.x;
    int i2 = idx * 2;
    float2 x = *(const float2*)(X + i2);
    *(half2*)(g_Ah + i2) = __halves2half2(__float2half_rn(x.x), __float2half_rn(x.y));
}
__global__ __launch_bounds__(256)
void vq_prep_b(const float* __restrict__ CB) {
    int idx = blockIdx.x * blockDim.x + threadIdx.x;
    int i2 = idx * 2;
    float2 x = *(const float2*)(CB + i2);
    *(half2*)(g_Bh + i2) = __halves2half2(__float2half_rn(x.x), __float2half_rn(x.y));
}

// ---------------- fp16 mma.sync GEMM (hi only): s = c2[k] - 2*dot ----------------
// BM=128, BN=256, BK=64 halves, 512 threads (16 warps 4x4), warp tile 32x64, 4 chunks.
#define BMg 128
#define BNg 256
#define CHUNKS 4
#define STAGES 3
#define SH 72                                   // halves per smem row (144 B; conflict-free ldsm)
#define A_STAGE_H (BMg * SH)                    // 9216 halves (18432 B)
#define B_STAGE_H (BNg * SH)                    // 18432 halves (36864 B)
#define STAGE_H   (A_STAGE_H + B_STAGE_H)       // 27648 halves (55296 B)
#define GEMM_SMEM_BYTES (STAGES * STAGE_H * 2 + BNg * 4)   // 166912

__global__ __launch_bounds__(512, 1)
void vq_mma_gemm() {
    extern __shared__ __align__(16) __half smem[];
    float* s_c2 = (float*)(smem + STAGES * STAGE_H);

    const int tid  = threadIdx.x;
    const int lane = tid & 31;
    const int wid  = tid >> 5;
    const int warp_row = wid & 3;
    const int warp_col = wid >> 2;
    const int bn = blockIdx.x;      // 0..3
    const int bm = blockIdx.y;      // 0..255

    if (tid < BNg) s_c2[tid] = g_c2[bn * BNg + tid];

    const __half* Abase = g_Ah + (size_t)(bm * BMg) * DIM;
    const __half* Bbase = g_Bh + (size_t)(bn * BNg) * DIM;
    const uint32_t sbase = smem_u32(smem);

    auto load_chunk = [&](int c) {
        const int stage = c % STAGES;
        const uint32_t dA = sbase + stage * (STAGE_H * 2);
        const uint32_t dB = dA + A_STAGE_H * 2;
        const int colb = c * 128;    // byte offset within 512-byte row
        #pragma unroll
        for (int i = 0; i < 2; i++) {   // A: 128 rows x 128 B = 1024 x 16B
            int idx = tid + i * 512;
            int row = idx >> 3, c16 = idx & 7;
            cp_async16(dA + row * (SH * 2) + c16 * 16,
                       (const char*)Abase + (size_t)row * (DIM * 2) + colb + c16 * 16);
        }
        #pragma unroll
        for (int i = 0; i < 4; i++) {   // B: 256 rows x 128 B = 2048 x 16B
            int idx = tid + i * 512;
            int row = idx >> 3, c16 = idx & 7;
            cp_async16(dB + row * (SH * 2) + c16 * 16,
                       (const char*)Bbase + (size_t)row * (DIM * 2) + colb + c16 * 16);
        }
        cp_commit();
    };

    float acc[2][8][4];
    #pragma unroll
    for (int mt = 0; mt < 2; mt++)
        #pragma unroll
        for (int nn = 0; nn < 8; nn++)
            #pragma unroll
            for (int j = 0; j < 4; j++) acc[mt][nn][j] = 0.f;

    load_chunk(0);
    load_chunk(1);

    const int grp = lane >> 3;
    const int rin = lane & 7;

    for (int c = 0; c < CHUNKS; c++) {
        if (c + 1 < CHUNKS) cp_wait<1>(); else cp_wait<0>();
        __syncthreads();
        if (c + 2 < CHUNKS) load_chunk(c + 2);

        const int stage = c % STAGES;
        const uint32_t aS = sbase + stage * (STAGE_H * 2);
        const uint32_t bS = aS + A_STAGE_H * 2;

        #pragma unroll
        for (int ks = 0; ks < 4; ks++) {
            const uint32_t kbyte = ks * 32;
            uint32_t a[2][4];
            #pragma unroll
            for (int mt = 0; mt < 2; mt++) {
                int arow = warp_row * 32 + mt * 16 + ((grp & 1) << 3) + rin;
                ldsm4(a[mt], aS + arow * (SH * 2) + kbyte + (grp >> 1) * 16);
            }
            uint32_t b[8][2];
            #pragma unroll
            for (int np = 0; np < 4; np++) {
                int brow = warp_col * 64 + np * 16 + ((grp >> 1) << 3) + rin;
                uint32_t b4[4];
                ldsm4(b4, bS + brow * (SH * 2) + kbyte + (grp & 1) * 16);
                b[np * 2][0]     = b4[0]; b[np * 2][1]     = b4[1];
                b[np * 2 + 1][0] = b4[2]; b[np * 2 + 1][1] = b4[3];
            }
            #pragma unroll
            for (int nn = 0; nn < 8; nn++) {
                mma_f16(acc[0][nn], a[0], b[nn][0], b[nn][1]);
                mma_f16(acc[1][nn], a[1], b[nn][0], b[nn][1]);
            }
        }
        __syncthreads();
    }

    // epilogue: s = c2[k] - 2*acc, stored fp16
    const int r4 = lane >> 2;
    const int c4 = lane & 3;
    #pragma unroll
    for (int mt = 0; mt < 2; mt++) {
        int row0 = bm * BMg + warp_row * 32 + mt * 16 + r4;
        #pragma unroll
        for (int nn = 0; nn < 8; nn++) {
            int ncl = warp_col * 64 + nn * 8 + c4 * 2;
            int col = bn * BNg + ncl;
            half2 h0 = __floats2half2_rn(s_c2[ncl]     - 2.f * acc[mt][nn][0],
                                         s_c2[ncl + 1] - 2.f * acc[mt][nn][1]);
            half2 h1 = __floats2half2_rn(s_c2[ncl]     - 2.f * acc[mt][nn][2],
                                         s_c2[ncl + 1] - 2.f * acc[mt][nn][3]);
            *(half2*)(g_Sh + (size_t)row0 * KCODES + col)       = h0;
            *(half2*)(g_Sh + (size_t)(row0 + 8) * KCODES + col) = h1;
        }
    }
}

// ---------------- warp-per-row: screen + exact refine + softmax + gather ----------------
// s-space: s = ||c||^2 - 2 x.c. Refined entries store d_exact - x2.
#define RW_BLOCKS 256
#define RW_WARPS  8
#define RW_ROWS   16

__global__ __launch_bounds__(256)
void vq_row_kernel(const float* __restrict__ X, const float* __restrict__ CB,
                   float* __restrict__ out_q, float* __restrict__ out_idx) {
    __shared__ float s_probs[KCODES];

    const int t = threadIdx.x;
    const int lane = t & 31;
    const int wid = t >> 5;

    #pragma unroll
    for (int i = t; i < KCODES; i += 256) s_probs[i] = 0.f;
    __syncthreads();

    float pacc[32];
    #pragma unroll
    for (int i = 0; i < 32; i++) pacc[i] = 0.f;
    float ent_sum = 0.f, lat_acc = 0.f;

    const int warp_g = blockIdx.x * RW_WARPS + wid;

    for (int r = 0; r < RW_ROWS; r++) {
        const int n = warp_g * RW_ROWS + r;
        const __half* srow = g_Sh + (size_t)n * KCODES;

        // approx distances (fp16 -> fp32): code id = m*128 + lane*4 + j
        float4 sv[8];
        #pragma unroll
        for (int m = 0; m < 8; m++) {
            uint2 u = *(const uint2*)(srow + m * 128 + lane * 4);
            float2 f0 = __half22float2(*(half2*)&u.x);
            float2 f1 = __half22float2(*(half2*)&u.y);
            sv[m].x = f0.x; sv[m].y = f0.y; sv[m].z = f1.x; sv[m].w = f1.y;
        }

        // preload x row slice + row norm x2
        const float* xrow = X + (size_t)n * DIM + lane * 8;
        const float4 xr0 = *(const float4*)(xrow);
        const float4 xr1 = *(const float4*)(xrow + 4);
        float x2 = xr0.x*xr0.x + xr0.y*xr0.y + xr0.z*xr0.z + xr0.w*xr0.w
                 + xr1.x*xr1.x + xr1.y*xr1.y + xr1.z*xr1.z + xr1.w*xr1.w;
        #pragma unroll
        for (int o = 16; o; o >>= 1) x2 += __shfl_xor_sync(0xffffffffu, x2, o);

        // approx min
        float mv = fminf(fminf(sv[0].x, sv[0].y), fminf(sv[0].z, sv[0].w));
        #pragma unroll
        for (int m = 1; m < 8; m++)
            mv = fminf(mv, fminf(fminf(sv[m].x, sv[m].y), fminf(sv[m].z, sv[m].w)));
        #pragma unroll
        for (int o = 16; o; o >>= 1)
            mv = fminf(mv, __shfl_xor_sync(0xffffffffu, mv, o));
        const float thr = mv + MARGIN;

        // candidate bitmask
        unsigned pend = 0;
        #pragma unroll
        for (int m = 0; m < 8; m++) {
            if (sv[m].x < thr) pend |= 1u << (m * 4 + 0);
            if (sv[m].y < thr) pend |= 1u << (m * 4 + 1);
            if (sv[m].z < thr) pend |= 1u << (m * 4 + 2);
            if (sv[m].w < thr) pend |= 1u << (m * 4 + 3);
        }

        // refine candidates with exact fp32 warp dots
        while (true) {
            unsigned anyb = __ballot_sync(0xffffffffu, pend != 0);
            if (!anyb) break;
            int src = __ffs(anyb) - 1;
            unsigned pb = __shfl_sync(0xffffffffu, pend, src);
            int slot = __ffs(pb) - 1;
            if (lane == src) pend &= pend - 1;
            int k = (slot >> 2) * 128 + src * 4 + (slot & 3);

            const float* crow = CB + (size_t)k * DIM + lane * 8;
            float4 c0 = *(const float4*)(crow);
            float4 c1 = *(const float4*)(crow + 4);
            float f0 = xr0.x - c0.x, f1 = xr0.y - c0.y, f2 = xr0.z - c0.z, f3 = xr0.w - c0.w;
            float f4 = xr1.x - c1.x, f5 = xr1.y - c1.y, f6 = xr1.z - c1.z, f7 = xr1.w - c1.w;
            float d = f0*f0 + f1*f1 + f2*f2 + f3*f3 + f4*f4 + f5*f5 + f6*f6 + f7*f7;
            #pragma unroll
            for (int o = 16; o; o >>= 1) d += __shfl_xor_sync(0xffffffffu, d, o);

            if (lane == src) {
                float snew = d - x2;
                int m = slot >> 2, j = slot & 3;
                #pragma unroll
                for (int mm = 0; mm < 8; mm++) if (mm == m) {
                    if (j == 0) sv[mm].x = snew;
                    else if (j == 1) sv[mm].y = snew;
                    else if (j == 2) sv[mm].z = snew;
                    else sv[mm].w = snew;
                }
            }
        }

        // exact argmin (earliest index wins ties)
        float bmv = sv[0].x; int bmi = lane * 4;
        #pragma unroll
        for (int m = 0; m < 8; m++) {
            int base = m * 128 + lane * 4;
            if (sv[m].x < bmv) { bmv = sv[m].x; bmi = base; }
            if (sv[m].y < bmv) { bmv = sv[m].y; bmi = base + 1; }
            if (sv[m].z < bmv) { bmv = sv[m].z; bmi = base + 2; }
            if (sv[m].w < bmv) { bmv = sv[m].w; bmi = base + 3; }
        }
        #pragma unroll
        for (int o = 16; o; o >>= 1) {
            float ov = __shfl_xor_sync(0xffffffffu, bmv, o);
            int   oi = __shfl_xor_sync(0xffffffffu, bmi, o);
            if (ov < bmv || (ov == bmv && oi < bmi)) { bmv = ov; bmi = oi; }
        }

        // softmax stats
        float e[32];
        float z = 0.f, s1 = 0.f;
        #pragma unroll
        for (int m = 0; m < 8; m++) {
            float d0 = sv[m].x - bmv, d1 = sv[m].y - bmv;
            float d2 = sv[m].z - bmv, d3 = sv[m].w - bmv;
            float e0 = expf(-100.f * d0);
            float e1 = expf(-100.f * d1);
            float e2 = expf(-100.f * d2);
            float e3 = expf(-100.f * d3);
            e[m * 4 + 0] = e0; e[m * 4 + 1] = e1; e[m * 4 + 2] = e2; e[m * 4 + 3] = e3;
            z  += e0 + e1 + e2 + e3;
            s1 += e0 * d0 + e1 * d1 + e2 * d2 + e3 * d3;
        }
        #pragma unroll
        for (int o = 16; o; o >>= 1) {
            z  += __shfl_xor_sync(0xffffffffu, z, o);
            s1 += __shfl_xor_sync(0xffffffffu, s1, o);
        }
        const float invZ = 1.f / z;
        #pragma unroll
        for (int i = 0; i < 32; i++) pacc[i] += e[i] * invZ;

        // gather quantized row; latent loss = bmv + x2
        const float* crow = CB + (size_t)bmi * DIM + lane * 8;
        float4 q0 = *(const float4*)(crow);
        float4 q1 = *(const float4*)(crow + 4);
        *(float4*)(out_q + (size_t)n * DIM + lane * 8)     = q0;
        *(float4*)(out_q + (size_t)n * DIM + lane * 8 + 4) = q1;

        if (lane == 0) {
            ent_sum += 100.f * (s1 * invZ) + logf(z);
            lat_acc += bmv + x2;
            if (out_idx) out_idx[n] = (float)bmi;
        }
    }

    #pragma unroll
    for (int m = 0; m < 8; m++) {
        int base = m * 128 + lane * 4;
        atomicAdd(&s_probs[base + 0], pacc[m * 4 + 0]);
        atomicAdd(&s_probs[base + 1], pacc[m * 4 + 1]);
        atomicAdd(&s_probs[base + 2], pacc[m * 4 + 2]);
        atomicAdd(&s_probs[base + 3], pacc[m * 4 + 3]);
    }
    __syncthreads();
    #pragma unroll
    for (int i = t; i < KCODES; i += 256) atomicAdd(&g_probs[i], s_probs[i]);
    if (lane == 0) {
        atomicAdd(&g_scal[0], lat_acc);
        atomicAdd(&g_scal[1], ent_sum);
    }
}

// ---------------- finalize ----------------
__global__ void vq_finalize_kernel(float* __restrict__ out_loss) {
    __shared__ float warp_s[32];
    const int t = threadIdx.x;
    const int lane = t & 31;
    const int wid = t >> 5;

    float p = g_probs[t] * (1.0f / (float)N_ROWS);
    float contrib = -p * logf(p + 1e-5f);
    #pragma unroll
    for (int o = 16; o; o >>= 1) contrib += __shfl_down_sync(0xffffffffu, contrib, o);
    if (lane == 0) warp_s[wid] = contrib;
    __syncthreads();
    if (wid == 0) {
        float v = warp_s[lane];
        #pragma unroll
        for (int o = 16; o; o >>= 1) v += __shfl_down_sync(0xffffffffu, v, o);
        if (lane == 0 && out_loss) {
            float avg_entropy = v;
            float sample_entropy = g_scal[1] * (1.0f / (float)N_ROWS);
            float mean_lat = g_scal[0] * (1.0f / ((float)N_ROWS * (float)DIM));
            float ent_loss = sample_entropy - avg_entropy;
            *out_loss = 1.25f * mean_lat + 0.1f * ent_loss;
        }
    }
}

// ---------------- launch ----------------
extern "C" void kernel_launch(void* const* d_in, const int* in_sizes, int n_in,
                              void* d_out, int out_size) {
    const float* X  = (const float*)d_in[0];
    const float* CB = (const float*)d_in[1];
    float* out = (float*)d_out;

    float* out_q    = out;
    float* out_loss = (out_size >= N_ROWS * DIM + 1) ? (out + (size_t)N_ROWS * DIM) : nullptr;
    float* out_idx  = (out_size >= N_ROWS * DIM + 1 + N_ROWS) ? (out + (size_t)N_ROWS * DIM + 1) : nullptr;

    static int smem_set = 0;
    if (!smem_set) {
        cudaFuncSetAttribute(vq_mma_gemm, cudaFuncAttributeMaxDynamicSharedMemorySize,
                             GEMM_SMEM_BYTES);
        smem_set = 1;
    }

    vq_init_kernel<<<128, 256>>>(CB);
    vq_prep_a<<<(N_ROWS * DIM / 2) / 256, 256>>>(X);
    vq_prep_b<<<(KCODES * DIM / 2) / 256, 256>>>(CB);
    dim3 g(KCODES / BNg, N_ROWS / BMg);
    vq_mma_gemm<<<g, 512, GEMM_SMEM_BYTES>>>();
    vq_row_kernel<<<RW_BLOCKS, 256>>>(X, CB, out_q, out_idx);
    vq_finalize_kernel<<<1, 1024>>>(out_loss);
}

// round 10
// speedup vs baseline: 4.6838x; 1.1310x over previous
#include <cuda_runtime.h>
#include <cuda_fp16.h>
#include <math.h>
#include <stdint.h>

#define N_ROWS 32768
#define DIM    256
#define KCODES 1024
#define MARGIN 0.5f

// ---------------- device scratch ----------------
__device__ __half g_Ah[(size_t)N_ROWS * DIM];      // X hi  (16 MB)
__device__ __half g_Bh[(size_t)KCODES * DIM];      // CB hi (0.5 MB)
__device__ float  g_c2[KCODES];
__device__ float  g_probs[KCODES];
__device__ float  g_scal[2];

// ---------------- PTX helpers (sm_100-safe, no 'a' features) ----------------
__device__ __forceinline__ uint32_t smem_u32(const void* p) {
    uint32_t a;
    asm("{ .reg .u64 t; cvta.to.shared.u64 t, %1; cvt.u32.u64 %0, t; }" : "=r"(a) : "l"(p));
    return a;
}
__device__ __forceinline__ void cp_async16(uint32_t dst, const void* src) {
    asm volatile("cp.async.cg.shared.global [%0], [%1], 16;" :: "r"(dst), "l"(src) : "memory");
}
__device__ __forceinline__ void cp_commit() {
    asm volatile("cp.async.commit_group;" ::: "memory");
}
template <int N>
__device__ __forceinline__ void cp_wait() {
    asm volatile("cp.async.wait_group %0;" :: "n"(N) : "memory");
}
__device__ __forceinline__ void ldsm4(uint32_t* r, uint32_t addr) {
    asm volatile("ldmatrix.sync.aligned.m8n8.x4.shared.b16 {%0,%1,%2,%3}, [%4];"
                 : "=r"(r[0]), "=r"(r[1]), "=r"(r[2]), "=r"(r[3]) : "r"(addr));
}
__device__ __forceinline__ void mma_f16(float* d, const uint32_t* a, uint32_t b0, uint32_t b1) {
    asm volatile(
        "mma.sync.aligned.m16n8k16.row.col.f32.f16.f16.f32 "
        "{%0,%1,%2,%3}, {%4,%5,%6,%7}, {%8,%9}, {%0,%1,%2,%3};"
        : "+f"(d[0]), "+f"(d[1]), "+f"(d[2]), "+f"(d[3])
        : "r"(a[0]), "r"(a[1]), "r"(a[2]), "r"(a[3]), "r"(b0), "r"(b1));
}
// monotone float<->uint encoding for atomicMin on possibly-negative floats
__device__ __forceinline__ unsigned fenc(float f) {
    unsigned u = __float_as_uint(f);
    return (u & 0x80000000u) ? ~u : (u | 0x80000000u);
}
__device__ __forceinline__ float fdec(unsigned e) {
    unsigned u = (e & 0x80000000u) ? (e ^ 0x80000000u) : ~e;
    return __uint_as_float(u);
}

// ---------------- init: zero accumulators + codebook norms ----------------
__global__ void vq_init_kernel(const float* __restrict__ CB) {
    int gtid = blockIdx.x * blockDim.x + threadIdx.x;
    if (gtid < KCODES) g_probs[gtid] = 0.f;
    if (gtid < 2) g_scal[gtid] = 0.f;
    int wid = gtid >> 5;
    int lane = gtid & 31;
    if (wid < KCODES) {
        const float* c = CB + (size_t)wid * DIM;
        float s = 0.f;
        for (int i = lane; i < DIM; i += 32) { float v = c[i]; s += v * v; }
        #pragma unroll
        for (int o = 16; o; o >>= 1) s += __shfl_down_sync(0xffffffffu, s, o);
        if (lane == 0) g_c2[wid] = s;
    }
}

// ---------------- prep: fp16 hi conversion ----------------
__global__ __launch_bounds__(256)
void vq_prep_a(const float* __restrict__ X) {
    int idx = blockIdx.x * blockDim.x + threadIdx.x;
    int i2 = idx * 2;
    float2 x = *(const float2*)(X + i2);
    *(half2*)(g_Ah + i2) = __halves2half2(__float2half_rn(x.x), __float2half_rn(x.y));
}
__global__ __launch_bounds__(256)
void vq_prep_b(const float* __restrict__ CB) {
    int idx = blockIdx.x * blockDim.x + threadIdx.x;
    int i2 = idx * 2;
    float2 x = *(const float2*)(CB + i2);
    *(half2*)(g_Bh + i2) = __halves2half2(__float2half_rn(x.x), __float2half_rn(x.y));
}

// ---------------- fused kernel ----------------
// Each CTA: 128 rows x all 1024 codes. 512 threads, 16 warps (4x4), warp tile 32x64.
// Column chunks of 256 codes (bn=0..3); K=256 in 4 k-chunks of 64 halves -> 16 pipeline steps.
// A (128x256 fp16) persistent in smem; B 3-stage cp.async pipeline.
// Screening: per-row running min (encoded atomicMin) + candidate list (<=32/row).
// Phase 2: warp-per-row exact fp32 refine, softmax over candidates, gather, loss partials.
#define SH_A_B  528                   // bytes per A smem row (264 halves)
#define SH_B_B  144                   // bytes per B smem row (72 halves)
#define A_BYTES (128 * SH_A_B)        // 67584
#define B_STAGE_BYTES (256 * SH_B_B)  // 36864
#define OFF_C2     178176
#define OFF_PROBS  182272
#define OFF_DSCR   186368
#define OFF_RUNMIN 188416
#define OFF_CNT    188928
#define OFF_CAND   189440
#define FUSED_SMEM 197632

__global__ __launch_bounds__(512, 1)
void vq_fused(const float* __restrict__ X, const float* __restrict__ CB,
              float* __restrict__ out_q, float* __restrict__ out_idx) {
    extern __shared__ __align__(16) char smem[];
    float*    s_c2     = (float*)(smem + OFF_C2);
    float*    s_probs  = (float*)(smem + OFF_PROBS);
    float*    s_dscr   = (float*)(smem + OFF_DSCR);      // [16 warps][32]
    unsigned* s_runmin = (unsigned*)(smem + OFF_RUNMIN); // [128] encoded
    int*      s_cnt    = (int*)(smem + OFF_CNT);         // [128]
    unsigned short* s_cand = (unsigned short*)(smem + OFF_CAND); // [128][32]

    const int tid  = threadIdx.x;
    const int lane = tid & 31;
    const int wid  = tid >> 5;
    const int warp_row = wid & 3;
    const int warp_col = wid >> 2;
    const int bm = blockIdx.x;          // 0..255
    const uint32_t sbase = smem_u32(smem);

    // ---- init shared state ----
    for (int i = tid; i < KCODES; i += 512) { s_c2[i] = g_c2[i]; s_probs[i] = 0.f; }
    if (tid < 128) { s_runmin[tid] = 0xFFFFFFFFu; s_cnt[tid] = 0; }

    // ---- A load (persistent): 128 rows x 512B ----
    const __half* Abase = g_Ah + (size_t)(bm * 128) * DIM;
    #pragma unroll
    for (int i = 0; i < 8; i++) {
        int idx = tid + i * 512;
        int row = idx >> 5, c16 = idx & 31;
        cp_async16(sbase + row * SH_A_B + c16 * 16,
                   Abase + (size_t)row * DIM + c16 * 8);
    }
    cp_commit();

    auto load_B = [&](int kcg) {
        const int bn = kcg >> 2, kc = kcg & 3, stage = kcg % 3;
        const uint32_t dB = sbase + A_BYTES + stage * B_STAGE_BYTES;
        #pragma unroll
        for (int i = 0; i < 4; i++) {
            int idx = tid + i * 512;
            int row = idx >> 3, c16 = idx & 7;
            cp_async16(dB + row * SH_B_B + c16 * 16,
                       g_Bh + (size_t)(bn * 256 + row) * DIM + kc * 64 + c16 * 8);
        }
        cp_commit();
    };

    load_B(0);
    load_B(1);

    float acc[2][8][4];
    #pragma unroll
    for (int mt = 0; mt < 2; mt++)
        #pragma unroll
        for (int nn = 0; nn < 8; nn++)
            #pragma unroll
            for (int j = 0; j < 4; j++) acc[mt][nn][j] = 0.f;

    const int grp = lane >> 3;
    const int rin = lane & 7;
    const int r4 = lane >> 2;
    const int c4 = lane & 3;

    // ---- phase 1: 16 pipeline steps (4 bn chunks x 4 k-chunks) ----
    for (int kcg = 0; kcg < 16; kcg++) {
        if (kcg < 15) cp_wait<1>(); else cp_wait<0>();
        __syncthreads();
        if (kcg + 2 < 16) load_B(kcg + 2);

        const int kc = kcg & 3, stage = kcg % 3;
        const uint32_t bS = sbase + A_BYTES + stage * B_STAGE_BYTES;

        #pragma unroll
        for (int ks = 0; ks < 4; ks++) {
            const uint32_t kbA = kc * 128 + ks * 32;
            const uint32_t kbB = ks * 32;
            uint32_t a[2][4];
            #pragma unroll
            for (int mt = 0; mt < 2; mt++) {
                int arow = warp_row * 32 + mt * 16 + ((grp & 1) << 3) + rin;
                ldsm4(a[mt], sbase + arow * SH_A_B + kbA + (grp >> 1) * 16);
            }
            uint32_t b[8][2];
            #pragma unroll
            for (int np = 0; np < 4; np++) {
                int brow = warp_col * 64 + np * 16 + ((grp >> 1) << 3) + rin;
                uint32_t b4[4];
                ldsm4(b4, bS + brow * SH_B_B + kbB + (grp & 1) * 16);
                b[np * 2][0]     = b4[0]; b[np * 2][1]     = b4[1];
                b[np * 2 + 1][0] = b4[2]; b[np * 2 + 1][1] = b4[3];
            }
            #pragma unroll
            for (int nn = 0; nn < 8; nn++) {
                mma_f16(acc[0][nn], a[0], b[nn][0], b[nn][1]);
                mma_f16(acc[1][nn], a[1], b[nn][0], b[nn][1]);
            }
        }

        if ((kcg & 3) == 3) {
            // ---- chunk epilogue: running min + candidates, straight from registers ----
            const int bn = kcg >> 2;
            // per-thread row-mins
            #pragma unroll
            for (int mt = 0; mt < 2; mt++) {
                int r0 = warp_row * 32 + mt * 16 + r4;
                float mn0 = 3.4e38f, mn1 = 3.4e38f;
                #pragma unroll
                for (int nn = 0; nn < 8; nn++) {
                    int kb = bn * 256 + warp_col * 64 + nn * 8 + c4 * 2;
                    float s00 = s_c2[kb]     - 2.f * acc[mt][nn][0];
                    float s01 = s_c2[kb + 1] - 2.f * acc[mt][nn][1];
                    float s10 = s_c2[kb]     - 2.f * acc[mt][nn][2];
                    float s11 = s_c2[kb + 1] - 2.f * acc[mt][nn][3];
                    mn0 = fminf(mn0, fminf(s00, s01));
                    mn1 = fminf(mn1, fminf(s10, s11));
                }
                atomicMin(&s_runmin[r0], fenc(mn0));
                atomicMin(&s_runmin[r0 + 8], fenc(mn1));
            }
            __syncthreads();
            // candidate check
            #pragma unroll
            for (int mt = 0; mt < 2; mt++) {
                int r0 = warp_row * 32 + mt * 16 + r4;
                float thr0 = fdec(s_runmin[r0]) + MARGIN;
                float thr1 = fdec(s_runmin[r0 + 8]) + MARGIN;
                #pragma unroll
                for (int nn = 0; nn < 8; nn++) {
                    int kb = bn * 256 + warp_col * 64 + nn * 8 + c4 * 2;
                    float s00 = s_c2[kb]     - 2.f * acc[mt][nn][0];
                    float s01 = s_c2[kb + 1] - 2.f * acc[mt][nn][1];
                    float s10 = s_c2[kb]     - 2.f * acc[mt][nn][2];
                    float s11 = s_c2[kb + 1] - 2.f * acc[mt][nn][3];
                    if (s00 < thr0) { int p = atomicAdd(&s_cnt[r0], 1);     if (p < 32) s_cand[r0 * 32 + p] = (unsigned short)kb; }
                    if (s01 < thr0) { int p = atomicAdd(&s_cnt[r0], 1);     if (p < 32) s_cand[r0 * 32 + p] = (unsigned short)(kb + 1); }
                    if (s10 < thr1) { int p = atomicAdd(&s_cnt[r0 + 8], 1); if (p < 32) s_cand[(r0 + 8) * 32 + p] = (unsigned short)kb; }
                    if (s11 < thr1) { int p = atomicAdd(&s_cnt[r0 + 8], 1); if (p < 32) s_cand[(r0 + 8) * 32 + p] = (unsigned short)(kb + 1); }
                }
            }
            // reset accumulators for next chunk
            #pragma unroll
            for (int mt = 0; mt < 2; mt++)
                #pragma unroll
                for (int nn = 0; nn < 8; nn++)
                    #pragma unroll
                    for (int j = 0; j < 4; j++) acc[mt][nn][j] = 0.f;
            __syncthreads();
        }
    }

    // ---- phase 2: warp-per-row exact refine + softmax + gather ----
    __syncthreads();
    float ent_sum = 0.f, lat_acc = 0.f;

    for (int rr = 0; rr < 8; rr++) {
        const int lrow = wid * 8 + rr;
        const int n = bm * 128 + lrow;

        const float* xrow = X + (size_t)n * DIM + lane * 8;
        const float4 xr0 = *(const float4*)(xrow);
        const float4 xr1 = *(const float4*)(xrow + 4);

        int cntr = s_cnt[lrow];
        if (cntr > 32) cntr = 32;

        float dmin = 3.4e38f; int kmin = 0x7fffffff;
        for (int j = 0; j < cntr; j++) {
            int k = s_cand[lrow * 32 + j];
            const float* crow = CB + (size_t)k * DIM + lane * 8;
            float4 c0 = *(const float4*)(crow);
            float4 c1 = *(const float4*)(crow + 4);
            float f0 = xr0.x - c0.x, f1 = xr0.y - c0.y, f2 = xr0.z - c0.z, f3 = xr0.w - c0.w;
            float f4 = xr1.x - c1.x, f5 = xr1.y - c1.y, f6 = xr1.z - c1.z, f7 = xr1.w - c1.w;
            float d = f0*f0 + f1*f1 + f2*f2 + f3*f3 + f4*f4 + f5*f5 + f6*f6 + f7*f7;
            #pragma unroll
            for (int o = 16; o; o >>= 1) d += __shfl_xor_sync(0xffffffffu, d, o);
            if (lane == 0) s_dscr[wid * 32 + j] = d;
            if (d < dmin || (d == dmin && k < kmin)) { dmin = d; kmin = k; }
        }
        __syncwarp();

        float Z = 0.f, S1 = 0.f;
        for (int j = 0; j < cntr; j++) {
            float dd = s_dscr[wid * 32 + j] - dmin;
            float e = expf(-100.f * dd);
            Z += e; S1 += e * dd;
        }

        if (lane == 0) {
            float invZ = 1.f / Z;
            for (int j = 0; j < cntr; j++) {
                float dd = s_dscr[wid * 32 + j] - dmin;
                atomicAdd(&s_probs[s_cand[lrow * 32 + j]], expf(-100.f * dd) * invZ);
            }
            ent_sum += 100.f * (S1 / Z) + logf(Z);
            lat_acc += dmin;
            if (out_idx) out_idx[n] = (float)kmin;
        }

        // gather quantized row
        const float* qrow = CB + (size_t)kmin * DIM + lane * 8;
        float4 q0 = *(const float4*)(qrow);
        float4 q1 = *(const float4*)(qrow + 4);
        *(float4*)(out_q + (size_t)n * DIM + lane * 8)     = q0;
        *(float4*)(out_q + (size_t)n * DIM + lane * 8 + 4) = q1;
    }

    __syncthreads();
    for (int i = tid; i < KCODES; i += 512) atomicAdd(&g_probs[i], s_probs[i]);
    if (lane == 0) {
        atomicAdd(&g_scal[0], lat_acc);
        atomicAdd(&g_scal[1], ent_sum);
    }
}

// ---------------- finalize ----------------
__global__ void vq_finalize_kernel(float* __restrict__ out_loss) {
    __shared__ float warp_s[32];
    const int t = threadIdx.x;
    const int lane = t & 31;
    const int wid = t >> 5;

    float p = g_probs[t] * (1.0f / (float)N_ROWS);
    float contrib = -p * logf(p + 1e-5f);
    #pragma unroll
    for (int o = 16; o; o >>= 1) contrib += __shfl_down_sync(0xffffffffu, contrib, o);
    if (lane == 0) warp_s[wid] = contrib;
    __syncthreads();
    if (wid == 0) {
        float v = warp_s[lane];
        #pragma unroll
        for (int o = 16; o; o >>= 1) v += __shfl_down_sync(0xffffffffu, v, o);
        if (lane == 0 && out_loss) {
            float avg_entropy = v;
            float sample_entropy = g_scal[1] * (1.0f / (float)N_ROWS);
            float mean_lat = g_scal[0] * (1.0f / ((float)N_ROWS * (float)DIM));
            float ent_loss = sample_entropy - avg_entropy;
            *out_loss = 1.25f * mean_lat + 0.1f * ent_loss;
        }
    }
}

// ---------------- launch ----------------
extern "C" void kernel_launch(void* const* d_in, const int* in_sizes, int n_in,
                              void* d_out, int out_size) {
    const float* X  = (const float*)d_in[0];
    const float* CB = (const float*)d_in[1];
    float* out = (float*)d_out;

    float* out_q    = out;
    float* out_loss = (out_size >= N_ROWS * DIM + 1) ? (out + (size_t)N_ROWS * DIM) : nullptr;
    float* out_idx  = (out_size >= N_ROWS * DIM + 1 + N_ROWS) ? (out + (size_t)N_ROWS * DIM + 1) : nullptr;

    static int smem_set = 0;
    if (!smem_set) {
        cudaFuncSetAttribute(vq_fused, cudaFuncAttributeMaxDynamicSharedMemorySize, FUSED_SMEM);
        smem_set = 1;
    }

    vq_init_kernel<<<128, 256>>>(CB);
    vq_prep_a<<<(N_ROWS * DIM / 2) / 256, 256>>>(X);
    vq_prep_b<<<(KCODES * DIM / 2) / 256, 256>>>(CB);
    vq_fused<<<N_ROWS / 128, 512, FUSED_SMEM>>>(X, CB, out_q, out_idx);
    vq_finalize_kernel<<<1, 1024>>>(out_loss);
}

// round 11
// speedup vs baseline: 4.9948x; 1.0664x over previous
#include <cuda_runtime.h>
#include <cuda_fp16.h>
#include <math.h>
#include <stdint.h>

#define N_ROWS 32768
#define DIM    256
#define KCODES 1024
#define MARGIN 0.5f
#define CAP    16

// ---------------- device scratch ----------------
__device__ __half g_Ah[(size_t)N_ROWS * DIM];      // X hi  (16 MB)
__device__ __half g_Bh[(size_t)KCODES * DIM];      // CB hi (0.5 MB)
__device__ float  g_c2[KCODES];
__device__ float  g_probs[KCODES];
__device__ float  g_scal[2];

// ---------------- PTX helpers (sm_100-safe, no 'a' features) ----------------
__device__ __forceinline__ uint32_t smem_u32(const void* p) {
    uint32_t a;
    asm("{ .reg .u64 t; cvta.to.shared.u64 t, %1; cvt.u32.u64 %0, t; }" : "=r"(a) : "l"(p));
    return a;
}
__device__ __forceinline__ void cp_async16(uint32_t dst, const void* src) {
    asm volatile("cp.async.cg.shared.global [%0], [%1], 16;" :: "r"(dst), "l"(src) : "memory");
}
__device__ __forceinline__ void cp_commit() {
    asm volatile("cp.async.commit_group;" ::: "memory");
}
template <int N>
__device__ __forceinline__ void cp_wait() {
    asm volatile("cp.async.wait_group %0;" :: "n"(N) : "memory");
}
__device__ __forceinline__ void ldsm4(uint32_t* r, uint32_t addr) {
    asm volatile("ldmatrix.sync.aligned.m8n8.x4.shared.b16 {%0,%1,%2,%3}, [%4];"
                 : "=r"(r[0]), "=r"(r[1]), "=r"(r[2]), "=r"(r[3]) : "r"(addr));
}
__device__ __forceinline__ void mma_f16(float* d, const uint32_t* a, uint32_t b0, uint32_t b1) {
    asm volatile(
        "mma.sync.aligned.m16n8k16.row.col.f32.f16.f16.f32 "
        "{%0,%1,%2,%3}, {%4,%5,%6,%7}, {%8,%9}, {%0,%1,%2,%3};"
        : "+f"(d[0]), "+f"(d[1]), "+f"(d[2]), "+f"(d[3])
        : "r"(a[0]), "r"(a[1]), "r"(a[2]), "r"(a[3]), "r"(b0), "r"(b1));
}
// monotone float<->uint encoding for atomicMin on possibly-negative floats
__device__ __forceinline__ unsigned fenc(float f) {
    unsigned u = __float_as_uint(f);
    return (u & 0x80000000u) ? ~u : (u | 0x80000000u);
}
__device__ __forceinline__ float fdec(unsigned e) {
    unsigned u = (e & 0x80000000u) ? (e ^ 0x80000000u) : ~e;
    return __uint_as_float(u);
}

// ---------------- init: zero accumulators + codebook norms ----------------
__global__ void vq_init_kernel(const float* __restrict__ CB) {
    int gtid = blockIdx.x * blockDim.x + threadIdx.x;
    if (gtid < KCODES) g_probs[gtid] = 0.f;
    if (gtid < 2) g_scal[gtid] = 0.f;
    int wid = gtid >> 5;
    int lane = gtid & 31;
    if (wid < KCODES) {
        const float* c = CB + (size_t)wid * DIM;
        float s = 0.f;
        for (int i = lane; i < DIM; i += 32) { float v = c[i]; s += v * v; }
        #pragma unroll
        for (int o = 16; o; o >>= 1) s += __shfl_down_sync(0xffffffffu, s, o);
        if (lane == 0) g_c2[wid] = s;
    }
}

// ---------------- prep: fp16 hi conversion ----------------
__global__ __launch_bounds__(256)
void vq_prep_a(const float* __restrict__ X) {
    int idx = blockIdx.x * blockDim.x + threadIdx.x;
    int i2 = idx * 2;
    float2 x = *(const float2*)(X + i2);
    *(half2*)(g_Ah + i2) = __halves2half2(__float2half_rn(x.x), __float2half_rn(x.y));
}
__global__ __launch_bounds__(256)
void vq_prep_b(const float* __restrict__ CB) {
    int idx = blockIdx.x * blockDim.x + threadIdx.x;
    int i2 = idx * 2;
    float2 x = *(const float2*)(CB + i2);
    *(half2*)(g_Bh + i2) = __halves2half2(__float2half_rn(x.x), __float2half_rn(x.y));
}

// ---------------- fused kernel (2 CTAs/SM) ----------------
// Each CTA: 128 rows x all 1024 codes. 256 threads, 8 warps (4 row x 2 col), warp tile 32x64.
// 8 bn chunks of 128 codes x 4 k-chunks of 64 halves = 32 pipeline steps, 2-stage B buffer.
// A (128x256 fp16, padded rows) persistent in smem. Screening: per-row running min +
// candidate list (<=16/row). Phase 2: warp-per-row exact fp32 refine + softmax + gather.
#define SH_A_B  528                    // bytes per A smem row (264 halves)
#define SH_B_B  144                    // bytes per B smem row (72 halves)
#define A_BYTES (128 * SH_A_B)         // 67584
#define B_STAGE_BYTES (128 * SH_B_B)   // 18432
#define OFF_B      67584
#define OFF_PROBS  104448
#define OFF_CAND   108544
#define OFF_CNT    112640
#define OFF_RUNMIN 113152
#define OFF_DSCR   113664
#define FUSED_SMEM 114176

__global__ __launch_bounds__(256, 2)
void vq_fused(const float* __restrict__ X, const float* __restrict__ CB,
              float* __restrict__ out_q, float* __restrict__ out_idx) {
    extern __shared__ __align__(16) char smem[];
    float*    s_probs  = (float*)(smem + OFF_PROBS);
    unsigned short* s_cand = (unsigned short*)(smem + OFF_CAND);  // [128][CAP]
    int*      s_cnt    = (int*)(smem + OFF_CNT);
    unsigned* s_runmin = (unsigned*)(smem + OFF_RUNMIN);
    float*    s_dscr   = (float*)(smem + OFF_DSCR);               // [8 warps][CAP]

    const int tid  = threadIdx.x;
    const int lane = tid & 31;
    const int wid  = tid >> 5;
    const int warp_row = wid & 3;     // 0..3
    const int warp_col = wid >> 2;    // 0..1
    const int bm = blockIdx.x;        // 0..255
    const uint32_t sbase = smem_u32(smem);

    // ---- init shared state ----
    for (int i = tid; i < KCODES; i += 256) s_probs[i] = 0.f;
    if (tid < 128) { s_runmin[tid] = 0xFFFFFFFFu; s_cnt[tid] = 0; }

    // ---- A load (persistent): 128 rows x 512B ----
    const __half* Abase = g_Ah + (size_t)(bm * 128) * DIM;
    #pragma unroll
    for (int i = 0; i < 16; i++) {
        int idx = tid + i * 256;
        int row = idx >> 5, c16 = idx & 31;
        cp_async16(sbase + row * SH_A_B + c16 * 16,
                   Abase + (size_t)row * DIM + c16 * 8);
    }
    cp_commit();

    auto load_B = [&](int step) {
        const int bn = step >> 2, kc = step & 3, stage = step & 1;
        const uint32_t dB = sbase + OFF_B + stage * B_STAGE_BYTES;
        #pragma unroll
        for (int i = 0; i < 4; i++) {
            int idx = tid + i * 256;
            int row = idx >> 3, c16 = idx & 7;
            cp_async16(dB + row * SH_B_B + c16 * 16,
                       g_Bh + (size_t)(bn * 128 + row) * DIM + kc * 64 + c16 * 8);
        }
        cp_commit();
    };

    load_B(0);
    load_B(1);

    float acc[2][8][4];
    #pragma unroll
    for (int mt = 0; mt < 2; mt++)
        #pragma unroll
        for (int nn = 0; nn < 8; nn++)
            #pragma unroll
            for (int j = 0; j < 4; j++) acc[mt][nn][j] = 0.f;

    const int grp = lane >> 3;
    const int rin = lane & 7;
    const int r4 = lane >> 2;
    const int c4 = lane & 3;

    // ---- phase 1: 32 pipeline steps (8 bn chunks x 4 k-chunks) ----
    for (int step = 0; step < 32; step++) {
        if (step < 31) cp_wait<1>(); else cp_wait<0>();
        __syncthreads();

        const int stage = step & 1;
        const uint32_t bS = sbase + OFF_B + stage * B_STAGE_BYTES;
        const uint32_t kcA = (step & 3) * 128;

        #pragma unroll
        for (int ks = 0; ks < 4; ks++) {
            const uint32_t kbA = kcA + ks * 32;
            const uint32_t kbB = ks * 32;
            uint32_t a[2][4];
            #pragma unroll
            for (int mt = 0; mt < 2; mt++) {
                int arow = warp_row * 32 + mt * 16 + ((grp & 1) << 3) + rin;
                ldsm4(a[mt], sbase + arow * SH_A_B + kbA + (grp >> 1) * 16);
            }
            uint32_t b[8][2];
            #pragma unroll
            for (int np = 0; np < 4; np++) {
                int brow = warp_col * 64 + np * 16 + ((grp >> 1) << 3) + rin;
                uint32_t b4[4];
                ldsm4(b4, bS + brow * SH_B_B + kbB + (grp & 1) * 16);
                b[np * 2][0]     = b4[0]; b[np * 2][1]     = b4[1];
                b[np * 2 + 1][0] = b4[2]; b[np * 2 + 1][1] = b4[3];
            }
            #pragma unroll
            for (int nn = 0; nn < 8; nn++) {
                mma_f16(acc[0][nn], a[0], b[nn][0], b[nn][1]);
                mma_f16(acc[1][nn], a[1], b[nn][0], b[nn][1]);
            }
        }

        if ((step & 3) == 3) {
            // ---- chunk epilogue: running min + candidate capture ----
            const int bn = step >> 2;
            float sval[2][16];
            #pragma unroll
            for (int mt = 0; mt < 2; mt++) {
                float mn0 = 3.4e38f, mn1 = 3.4e38f;
                #pragma unroll
                for (int nn = 0; nn < 8; nn++) {
                    int kb = bn * 128 + warp_col * 64 + nn * 8 + c4 * 2;
                    float c20 = g_c2[kb], c21 = g_c2[kb + 1];
                    float s00 = c20 - 2.f * acc[mt][nn][0];
                    float s01 = c21 - 2.f * acc[mt][nn][1];
                    float s10 = c20 - 2.f * acc[mt][nn][2];
                    float s11 = c21 - 2.f * acc[mt][nn][3];
                    sval[mt][nn * 2]     = s00;   // row r4,   pair (s00,s01)
                    sval[mt][nn * 2 + 1] = s01;
                    mn0 = fminf(mn0, fminf(s00, s01));
                    mn1 = fminf(mn1, fminf(s10, s11));
                    // stash row r4+8 values in registers via recompute later (kept: s10/s11 re-derived)
                }
                int r0 = warp_row * 32 + mt * 16 + r4;
                atomicMin(&s_runmin[r0], fenc(mn0));
                atomicMin(&s_runmin[r0 + 8], fenc(mn1));
            }
            __syncthreads();
            #pragma unroll
            for (int mt = 0; mt < 2; mt++) {
                int r0 = warp_row * 32 + mt * 16 + r4;
                float thr0 = fdec(s_runmin[r0]) + MARGIN;
                float thr1 = fdec(s_runmin[r0 + 8]) + MARGIN;
                #pragma unroll
                for (int nn = 0; nn < 8; nn++) {
                    int kb = bn * 128 + warp_col * 64 + nn * 8 + c4 * 2;
                    float s00 = sval[mt][nn * 2];
                    float s01 = sval[mt][nn * 2 + 1];
                    float s10 = g_c2[kb]     - 2.f * acc[mt][nn][2];
                    float s11 = g_c2[kb + 1] - 2.f * acc[mt][nn][3];
                    if (s00 < thr0) { int p = atomicAdd(&s_cnt[r0], 1);     if (p < CAP) s_cand[r0 * CAP + p] = (unsigned short)kb; }
                    if (s01 < thr0) { int p = atomicAdd(&s_cnt[r0], 1);     if (p < CAP) s_cand[r0 * CAP + p] = (unsigned short)(kb + 1); }
                    if (s10 < thr1) { int p = atomicAdd(&s_cnt[r0 + 8], 1); if (p < CAP) s_cand[(r0 + 8) * CAP + p] = (unsigned short)kb; }
                    if (s11 < thr1) { int p = atomicAdd(&s_cnt[r0 + 8], 1); if (p < CAP) s_cand[(r0 + 8) * CAP + p] = (unsigned short)(kb + 1); }
                }
            }
            #pragma unroll
            for (int mt = 0; mt < 2; mt++)
                #pragma unroll
                for (int nn = 0; nn < 8; nn++)
                    #pragma unroll
                    for (int j = 0; j < 4; j++) acc[mt][nn][j] = 0.f;
        }

        __syncthreads();
        if (step + 2 < 32) load_B(step + 2);
    }

    // ---- phase 2: warp-per-row exact refine + softmax + gather ----
    __syncthreads();
    float ent_sum = 0.f, lat_acc = 0.f;

    for (int rr = 0; rr < 16; rr++) {
        const int lrow = wid * 16 + rr;
        const int n = bm * 128 + lrow;

        const float* xrow = X + (size_t)n * DIM + lane * 8;
        const float4 xr0 = *(const float4*)(xrow);
        const float4 xr1 = *(const float4*)(xrow + 4);

        int cntr = s_cnt[lrow];
        if (cntr > CAP) cntr = CAP;

        float dmin = 3.4e38f; int kmin = 0x7fffffff;
        for (int j = 0; j < cntr; j++) {
            int k = s_cand[lrow * CAP + j];
            const float* crow = CB + (size_t)k * DIM + lane * 8;
            float4 c0 = *(const float4*)(crow);
            float4 c1 = *(const float4*)(crow + 4);
            float f0 = xr0.x - c0.x, f1 = xr0.y - c0.y, f2 = xr0.z - c0.z, f3 = xr0.w - c0.w;
            float f4 = xr1.x - c1.x, f5 = xr1.y - c1.y, f6 = xr1.z - c1.z, f7 = xr1.w - c1.w;
            float d = f0*f0 + f1*f1 + f2*f2 + f3*f3 + f4*f4 + f5*f5 + f6*f6 + f7*f7;
            #pragma unroll
            for (int o = 16; o; o >>= 1) d += __shfl_xor_sync(0xffffffffu, d, o);
            if (lane == 0) s_dscr[wid * CAP + j] = d;
            if (d < dmin || (d == dmin && k < kmin)) { dmin = d; kmin = k; }
        }
        __syncwarp();

        if (lane == 0) {
            float Z = 0.f, S1 = 0.f;
            for (int j = 0; j < cntr; j++) {
                float dd = s_dscr[wid * CAP + j] - dmin;
                float e = expf(-100.f * dd);
                Z += e; S1 += e * dd;
            }
            float invZ = 1.f / Z;
            for (int j = 0; j < cntr; j++) {
                float dd = s_dscr[wid * CAP + j] - dmin;
                atomicAdd(&s_probs[s_cand[lrow * CAP + j]], expf(-100.f * dd) * invZ);
            }
            ent_sum += 100.f * (S1 * invZ) + logf(Z);
            lat_acc += dmin;
            if (out_idx) out_idx[n] = (float)kmin;
        }

        // gather quantized row
        const float* qrow = CB + (size_t)kmin * DIM + lane * 8;
        float4 q0 = *(const float4*)(qrow);
        float4 q1 = *(const float4*)(qrow + 4);
        *(float4*)(out_q + (size_t)n * DIM + lane * 8)     = q0;
        *(float4*)(out_q + (size_t)n * DIM + lane * 8 + 4) = q1;
    }

    __syncthreads();
    for (int i = tid; i < KCODES; i += 256) {
        float v = s_probs[i];
        if (v != 0.f) atomicAdd(&g_probs[i], v);
    }
    if (lane == 0) {
        atomicAdd(&g_scal[0], lat_acc);
        atomicAdd(&g_scal[1], ent_sum);
    }
}

// ---------------- finalize ----------------
__global__ void vq_finalize_kernel(float* __restrict__ out_loss) {
    __shared__ float warp_s[32];
    const int t = threadIdx.x;
    const int lane = t & 31;
    const int wid = t >> 5;

    float p = g_probs[t] * (1.0f / (float)N_ROWS);
    float contrib = -p * logf(p + 1e-5f);
    #pragma unroll
    for (int o = 16; o; o >>= 1) contrib += __shfl_down_sync(0xffffffffu, contrib, o);
    if (lane == 0) warp_s[wid] = contrib;
    __syncthreads();
    if (wid == 0) {
        float v = warp_s[lane];
        #pragma unroll
        for (int o = 16; o; o >>= 1) v += __shfl_down_sync(0xffffffffu, v, o);
        if (lane == 0 && out_loss) {
            float avg_entropy = v;
            float sample_entropy = g_scal[1] * (1.0f / (float)N_ROWS);
            float mean_lat = g_scal[0] * (1.0f / ((float)N_ROWS * (float)DIM));
            float ent_loss = sample_entropy - avg_entropy;
            *out_loss = 1.25f * mean_lat + 0.1f * ent_loss;
        }
    }
}

// ---------------- launch ----------------
extern "C" void kernel_launch(void* const* d_in, const int* in_sizes, int n_in,
                              void* d_out, int out_size) {
    const float* X  = (const float*)d_in[0];
    const float* CB = (const float*)d_in[1];
    float* out = (float*)d_out;

    float* out_q    = out;
    float* out_loss = (out_size >= N_ROWS * DIM + 1) ? (out + (size_t)N_ROWS * DIM) : nullptr;
    float* out_idx  = (out_size >= N_ROWS * DIM + 1 + N_ROWS) ? (out + (size_t)N_ROWS * DIM + 1) : nullptr;

    static int smem_set = 0;
    if (!smem_set) {
        cudaFuncSetAttribute(vq_fused, cudaFuncAttributeMaxDynamicSharedMemorySize, FUSED_SMEM);
        smem_set = 1;
    }

    vq_init_kernel<<<128, 256>>>(CB);
    vq_prep_a<<<(N_ROWS * DIM / 2) / 256, 256>>>(X);
    vq_prep_b<<<(KCODES * DIM / 2) / 256, 256>>>(CB);
    vq_fused<<<N_ROWS / 128, 256, FUSED_SMEM>>>(X, CB, out_q, out_idx);
    vq_finalize_kernel<<<1, 1024>>>(out_loss);
}

// round 12
// speedup vs baseline: 5.2484x; 1.0508x over previous
#include <cuda_runtime.h>
#include <cuda_fp16.h>
#include <math.h>
#include <stdint.h>

#define N_ROWS 32768
#define DIM    256
#define KCODES 1024
#define MARGIN 0.5f
#define CAP    20

// ---------------- device scratch ----------------
__device__ __half g_Bh[(size_t)KCODES * DIM];      // CB hi (0.5 MB)
__device__ float  g_c2[KCODES];
__device__ float  g_probs[KCODES];
__device__ float  g_scal[2];

// ---------------- PTX helpers (sm_100-safe, no 'a' features) ----------------
__device__ __forceinline__ uint32_t smem_u32(const void* p) {
    uint32_t a;
    asm("{ .reg .u64 t; cvta.to.shared.u64 t, %1; cvt.u32.u64 %0, t; }" : "=r"(a) : "l"(p));
    return a;
}
__device__ __forceinline__ void cp_async16(uint32_t dst, const void* src) {
    asm volatile("cp.async.cg.shared.global [%0], [%1], 16;" :: "r"(dst), "l"(src) : "memory");
}
__device__ __forceinline__ void cp_commit() {
    asm volatile("cp.async.commit_group;" ::: "memory");
}
template <int N>
__device__ __forceinline__ void cp_wait() {
    asm volatile("cp.async.wait_group %0;" :: "n"(N) : "memory");
}
__device__ __forceinline__ void ldsm4(uint32_t* r, uint32_t addr) {
    asm volatile("ldmatrix.sync.aligned.m8n8.x4.shared.b16 {%0,%1,%2,%3}, [%4];"
                 : "=r"(r[0]), "=r"(r[1]), "=r"(r[2]), "=r"(r[3]) : "r"(addr));
}
__device__ __forceinline__ void mma_f16(float* d, const uint32_t* a, uint32_t b0, uint32_t b1) {
    asm volatile(
        "mma.sync.aligned.m16n8k16.row.col.f32.f16.f16.f32 "
        "{%0,%1,%2,%3}, {%4,%5,%6,%7}, {%8,%9}, {%0,%1,%2,%3};"
        : "+f"(d[0]), "+f"(d[1]), "+f"(d[2]), "+f"(d[3])
        : "r"(a[0]), "r"(a[1]), "r"(a[2]), "r"(a[3]), "r"(b0), "r"(b1));
}
// monotone float<->uint encoding for atomicMin on possibly-negative floats
__device__ __forceinline__ unsigned fenc(float f) {
    unsigned u = __float_as_uint(f);
    return (u & 0x80000000u) ? ~u : (u | 0x80000000u);
}
__device__ __forceinline__ float fdec(unsigned e) {
    unsigned u = (e & 0x80000000u) ? (e ^ 0x80000000u) : ~e;
    return __uint_as_float(u);     // NaN for the init pattern; fminf handles it
}

// ---------------- setup: zero accumulators + fp16 codebook + norms ----------------
__global__ __launch_bounds__(256)
void vq_setup(const float* __restrict__ CB) {
    int gtid = blockIdx.x * blockDim.x + threadIdx.x;   // 65536 threads
    if (gtid < KCODES) g_probs[gtid] = 0.f;
    if (gtid < 2) g_scal[gtid] = 0.f;
    // fp16 conversion of CB: 131072 float2, 2 per thread
    #pragma unroll
    for (int j = 0; j < 2; j++) {
        int i2 = (gtid + j * 65536) * 2;
        float2 x = *(const float2*)(CB + i2);
        *(half2*)(g_Bh + i2) = __floats2half2_rn(x.x, x.y);
    }
    // codebook norms: warp per code (first 1024 warps)
    int wid = gtid >> 5;
    int lane = gtid & 31;
    if (wid < KCODES) {
        const float* c = CB + (size_t)wid * DIM;
        float s = 0.f;
        for (int i = lane; i < DIM; i += 32) { float v = c[i]; s += v * v; }
        #pragma unroll
        for (int o = 16; o; o >>= 1) s += __shfl_down_sync(0xffffffffu, s, o);
        if (lane == 0) g_c2[wid] = s;
    }
}

// ---------------- fused kernel (2 CTAs/SM) ----------------
// Each CTA: 128 rows x all 1024 codes. 256 threads, 8 warps (4 row x 2 col), warp tile 32x64.
// A converted fp32->fp16 in-kernel into persistent smem. 8 bn chunks x 4 k-chunks = 32 steps,
// 2-stage B pipeline. Screening: per-row running min + candidate list (<=20/row), sync-free
// epilogue (threshold = min(stale runmin, own quad-min) + margin is always an upper bound).
// Phase 2: warp-per-row exact fp32 refine + softmax + gather.
#define SH_A_B  528                    // bytes per A smem row (264 halves)
#define SH_B_B  144                    // bytes per B smem row (72 halves)
#define A_BYTES (128 * SH_A_B)         // 67584
#define B_STAGE_BYTES (128 * SH_B_B)   // 18432
#define OFF_B      67584
#define OFF_PROBS  104448
#define OFF_CAND   108544              // 128*20*2 = 5120
#define OFF_CNT    113664
#define OFF_RUNMIN 114176
#define OFF_DSCR   114688              // 8*20*4 = 640
#define FUSED_SMEM 115328

__global__ __launch_bounds__(256, 2)
void vq_fused(const float* __restrict__ X, const float* __restrict__ CB,
              float* __restrict__ out_q, float* __restrict__ out_idx) {
    extern __shared__ __align__(16) char smem[];
    float*    s_probs  = (float*)(smem + OFF_PROBS);
    unsigned short* s_cand = (unsigned short*)(smem + OFF_CAND);  // [128][CAP]
    int*      s_cnt    = (int*)(smem + OFF_CNT);
    unsigned* s_runmin = (unsigned*)(smem + OFF_RUNMIN);
    float*    s_dscr   = (float*)(smem + OFF_DSCR);               // [8 warps][CAP]

    const int tid  = threadIdx.x;
    const int lane = tid & 31;
    const int wid  = tid >> 5;
    const int warp_row = wid & 3;     // 0..3
    const int warp_col = wid >> 2;    // 0..1
    const int bm = blockIdx.x;        // 0..255
    const uint32_t sbase = smem_u32(smem);

    // ---- init shared state ----
    for (int i = tid; i < KCODES; i += 256) s_probs[i] = 0.f;
    if (tid < 128) { s_runmin[tid] = 0xFFFFFFFFu; s_cnt[tid] = 0; }

    auto load_B = [&](int step) {
        const int bn = step >> 2, kc = step & 3, stage = step & 1;
        const uint32_t dB = sbase + OFF_B + stage * B_STAGE_BYTES;
        #pragma unroll
        for (int i = 0; i < 4; i++) {
            int idx = tid + i * 256;
            int row = idx >> 3, c16 = idx & 7;
            cp_async16(dB + row * SH_B_B + c16 * 16,
                       g_Bh + (size_t)(bn * 128 + row) * DIM + kc * 64 + c16 * 8);
        }
        cp_commit();
    };

    load_B(0);
    load_B(1);

    // ---- A conversion: X fp32 -> smem fp16 (overlaps B pipeline warmup) ----
    {
        const float* Xa = X + (size_t)(bm * 128) * DIM;
        #pragma unroll
        for (int i = 0; i < 32; i++) {
            int idx = tid + i * 256;          // 0..8191
            int row = idx >> 6;               // 0..127
            int c4i = idx & 63;               // 0..63 float4s per row
            float4 v = *(const float4*)(Xa + (size_t)row * DIM + c4i * 4);
            half2 h0 = __floats2half2_rn(v.x, v.y);
            half2 h1 = __floats2half2_rn(v.z, v.w);
            uint2 u;
            u.x = *(const uint32_t*)&h0;
            u.y = *(const uint32_t*)&h1;
            *(uint2*)(smem + row * SH_A_B + c4i * 8) = u;
        }
    }

    float acc[2][8][4];
    #pragma unroll
    for (int mt = 0; mt < 2; mt++)
        #pragma unroll
        for (int nn = 0; nn < 8; nn++)
            #pragma unroll
            for (int j = 0; j < 4; j++) acc[mt][nn][j] = 0.f;

    const int grp = lane >> 3;
    const int rin = lane & 7;
    const int r4 = lane >> 2;
    const int c4 = lane & 3;

    // ---- phase 1: 32 pipeline steps (8 bn chunks x 4 k-chunks) ----
    for (int step = 0; step < 32; step++) {
        if (step < 31) cp_wait<1>(); else cp_wait<0>();
        __syncthreads();

        const uint32_t bS = sbase + OFF_B + (step & 1) * B_STAGE_BYTES;
        const uint32_t kcA = (step & 3) * 128;

        #pragma unroll
        for (int ks = 0; ks < 4; ks++) {
            const uint32_t kbA = kcA + ks * 32;
            const uint32_t kbB = ks * 32;
            uint32_t a[2][4];
            #pragma unroll
            for (int mt = 0; mt < 2; mt++) {
                int arow = warp_row * 32 + mt * 16 + ((grp & 1) << 3) + rin;
                ldsm4(a[mt], sbase + arow * SH_A_B + kbA + (grp >> 1) * 16);
            }
            uint32_t b[8][2];
            #pragma unroll
            for (int np = 0; np < 4; np++) {
                int brow = warp_col * 64 + np * 16 + ((grp >> 1) << 3) + rin;
                uint32_t b4[4];
                ldsm4(b4, bS + brow * SH_B_B + kbB + (grp & 1) * 16);
                b[np * 2][0]     = b4[0]; b[np * 2][1]     = b4[1];
                b[np * 2 + 1][0] = b4[2]; b[np * 2 + 1][1] = b4[3];
            }
            #pragma unroll
            for (int nn = 0; nn < 8; nn++) {
                mma_f16(acc[0][nn], a[0], b[nn][0], b[nn][1]);
                mma_f16(acc[1][nn], a[1], b[nn][0], b[nn][1]);
            }
        }

        if ((step & 3) == 3) {
            // ---- sync-free chunk epilogue ----
            const int bn = step >> 2;
            #pragma unroll
            for (int mt = 0; mt < 2; mt++) {
                const int r0 = warp_row * 32 + mt * 16 + r4;
                // pass 1: per-thread row minima
                float mn0 = 3.4e38f, mn1 = 3.4e38f;
                #pragma unroll
                for (int nn = 0; nn < 8; nn++) {
                    int kb = bn * 128 + warp_col * 64 + nn * 8 + c4 * 2;
                    float c20 = g_c2[kb], c21 = g_c2[kb + 1];
                    mn0 = fminf(mn0, fminf(c20 - 2.f * acc[mt][nn][0], c21 - 2.f * acc[mt][nn][1]));
                    mn1 = fminf(mn1, fminf(c20 - 2.f * acc[mt][nn][2], c21 - 2.f * acc[mt][nn][3]));
                }
                // quad-reduce across the 4 c4 lanes of this row
                mn0 = fminf(mn0, __shfl_xor_sync(0xffffffffu, mn0, 1));
                mn0 = fminf(mn0, __shfl_xor_sync(0xffffffffu, mn0, 2));
                mn1 = fminf(mn1, __shfl_xor_sync(0xffffffffu, mn1, 1));
                mn1 = fminf(mn1, __shfl_xor_sync(0xffffffffu, mn1, 2));
                // thresholds: any upper bound of final min works (stale read is fine)
                float thr0 = fminf(fdec(s_runmin[r0]), mn0) + MARGIN;
                float thr1 = fminf(fdec(s_runmin[r0 + 8]), mn1) + MARGIN;
                // pass 2: capture candidates
                #pragma unroll
                for (int nn = 0; nn < 8; nn++) {
                    int kb = bn * 128 + warp_col * 64 + nn * 8 + c4 * 2;
                    float c20 = g_c2[kb], c21 = g_c2[kb + 1];
                    float s00 = c20 - 2.f * acc[mt][nn][0];
                    float s01 = c21 - 2.f * acc[mt][nn][1];
                    float s10 = c20 - 2.f * acc[mt][nn][2];
                    float s11 = c21 - 2.f * acc[mt][nn][3];
                    if (s00 < thr0) { int p = atomicAdd(&s_cnt[r0], 1);     if (p < CAP) s_cand[r0 * CAP + p] = (unsigned short)kb; }
                    if (s01 < thr0) { int p = atomicAdd(&s_cnt[r0], 1);     if (p < CAP) s_cand[r0 * CAP + p] = (unsigned short)(kb + 1); }
                    if (s10 < thr1) { int p = atomicAdd(&s_cnt[r0 + 8], 1); if (p < CAP) s_cand[(r0 + 8) * CAP + p] = (unsigned short)kb; }
                    if (s11 < thr1) { int p = atomicAdd(&s_cnt[r0 + 8], 1); if (p < CAP) s_cand[(r0 + 8) * CAP + p] = (unsigned short)(kb + 1); }
                }
                if (c4 == 0) {
                    atomicMin(&s_runmin[r0], fenc(mn0));
                    atomicMin(&s_runmin[r0 + 8], fenc(mn1));
                }
                // reset accumulators
                #pragma unroll
                for (int nn = 0; nn < 8; nn++)
                    #pragma unroll
                    for (int j = 0; j < 4; j++) acc[mt][nn][j] = 0.f;
            }
        }

        __syncthreads();
        if (step + 2 < 32) load_B(step + 2);
    }

    // ---- phase 2: warp-per-row exact refine + softmax + gather ----
    __syncthreads();
    float ent_sum = 0.f, lat_acc = 0.f;

    for (int rr = 0; rr < 16; rr++) {
        const int lrow = wid * 16 + rr;
        const int n = bm * 128 + lrow;

        const float* xrow = X + (size_t)n * DIM + lane * 8;
        const float4 xr0 = *(const float4*)(xrow);
        const float4 xr1 = *(const float4*)(xrow + 4);

        int cntr = s_cnt[lrow];
        if (cntr > CAP) cntr = CAP;

        float dmin = 3.4e38f; int kmin = 0x7fffffff;
        for (int j = 0; j < cntr; j++) {
            int k = s_cand[lrow * CAP + j];
            const float* crow = CB + (size_t)k * DIM + lane * 8;
            float4 c0 = *(const float4*)(crow);
            float4 c1 = *(const float4*)(crow + 4);
            float f0 = xr0.x - c0.x, f1 = xr0.y - c0.y, f2 = xr0.z - c0.z, f3 = xr0.w - c0.w;
            float f4 = xr1.x - c1.x, f5 = xr1.y - c1.y, f6 = xr1.z - c1.z, f7 = xr1.w - c1.w;
            float d = f0*f0 + f1*f1 + f2*f2 + f3*f3 + f4*f4 + f5*f5 + f6*f6 + f7*f7;
            #pragma unroll
            for (int o = 16; o; o >>= 1) d += __shfl_xor_sync(0xffffffffu, d, o);
            if (lane == 0) s_dscr[wid * CAP + j] = d;
            if (d < dmin || (d == dmin && k < kmin)) { dmin = d; kmin = k; }
        }
        __syncwarp();

        if (lane == 0) {
            float Z = 0.f, S1 = 0.f;
            for (int j = 0; j < cntr; j++) {
                float dd = s_dscr[wid * CAP + j] - dmin;
                float e = expf(-100.f * dd);
                Z += e; S1 += e * dd;
            }
            float invZ = 1.f / Z;
            for (int j = 0; j < cntr; j++) {
                float dd = s_dscr[wid * CAP + j] - dmin;
                atomicAdd(&s_probs[s_cand[lrow * CAP + j]], expf(-100.f * dd) * invZ);
            }
            ent_sum += 100.f * (S1 * invZ) + logf(Z);
            lat_acc += dmin;
            if (out_idx) out_idx[n] = (float)kmin;
        }

        // gather quantized row
        const float* qrow = CB + (size_t)kmin * DIM + lane * 8;
        float4 q0 = *(const float4*)(qrow);
        float4 q1 = *(const float4*)(qrow + 4);
        *(float4*)(out_q + (size_t)n * DIM + lane * 8)     = q0;
        *(float4*)(out_q + (size_t)n * DIM + lane * 8 + 4) = q1;
    }

    __syncthreads();
    for (int i = tid; i < KCODES; i += 256) {
        float v = s_probs[i];
        if (v != 0.f) atomicAdd(&g_probs[i], v);
    }
    if (lane == 0) {
        atomicAdd(&g_scal[0], lat_acc);
        atomicAdd(&g_scal[1], ent_sum);
    }
}

// ---------------- finalize ----------------
__global__ void vq_finalize_kernel(float* __restrict__ out_loss) {
    __shared__ float warp_s[32];
    const int t = threadIdx.x;
    const int lane = t & 31;
    const int wid = t >> 5;

    float p = g_probs[t] * (1.0f / (float)N_ROWS);
    float contrib = -p * logf(p + 1e-5f);
    #pragma unroll
    for (int o = 16; o; o >>= 1) contrib += __shfl_down_sync(0xffffffffu, contrib, o);
    if (lane == 0) warp_s[wid] = contrib;
    __syncthreads();
    if (wid == 0) {
        float v = warp_s[lane];
        #pragma unroll
        for (int o = 16; o; o >>= 1) v += __shfl_down_sync(0xffffffffu, v, o);
        if (lane == 0 && out_loss) {
            float avg_entropy = v;
            float sample_entropy = g_scal[1] * (1.0f / (float)N_ROWS);
            float mean_lat = g_scal[0] * (1.0f / ((float)N_ROWS * (float)DIM));
            float ent_loss = sample_entropy - avg_entropy;
            *out_loss = 1.25f * mean_lat + 0.1f * ent_loss;
        }
    }
}

// ---------------- launch ----------------
extern "C" void kernel_launch(void* const* d_in, const int* in_sizes, int n_in,
                              void* d_out, int out_size) {
    const float* X  = (const float*)d_in[0];
    const float* CB = (const float*)d_in[1];
    float* out = (float*)d_out;

    float* out_q    = out;
    float* out_loss = (out_size >= N_ROWS * DIM + 1) ? (out + (size_t)N_ROWS * DIM) : nullptr;
    float* out_idx  = (out_size >= N_ROWS * DIM + 1 + N_ROWS) ? (out + (size_t)N_ROWS * DIM + 1) : nullptr;

    static int smem_set = 0;
    if (!smem_set) {
        cudaFuncSetAttribute(vq_fused, cudaFuncAttributeMaxDynamicSharedMemorySize, FUSED_SMEM);
        smem_set = 1;
    }

    vq_setup<<<256, 256>>>(CB);
    vq_fused<<<N_ROWS / 128, 256, FUSED_SMEM>>>(X, CB, out_q, out_idx);
    vq_finalize_kernel<<<1, 1024>>>(out_loss);
}